// round 10
// baseline (speedup 1.0000x reference)
#include <cuda_runtime.h>
#include <math.h>
#include <stdint.h>

#define BB 4
#define LL 1024
#define HID 512
#define HEADS 8
#define HD 64

// Scratch (device globals: allocation-free)
__device__ float g_q[BB*LL*HID];
__device__ float g_k[BB*LL*HID];
__device__ float g_v[BB*LL*HID];
__device__ float g_ctx[BB*LL*HID];

struct GArgs {
    const float* A[3];
    const float* W[3];
    const float* bias[3];
    float* C[3];
    int round_out[3];   // 1: store tf32-rounded C (for q/k/v scratch)
};

// tf32 round (rna) -> 32-bit pattern in a b32 register
__device__ __forceinline__ uint32_t cvt_tf32(float x) {
    uint32_t r;
    asm("cvt.rna.tf32.f32 %0, %1;" : "=r"(r) : "f"(x));
    return r;
}
__device__ __forceinline__ uint32_t fu(float x) { return __float_as_uint(x); }
__device__ __forceinline__ uint4 cvt4(float4 v) {
    uint4 u;
    u.x = cvt_tf32(v.x); u.y = cvt_tf32(v.y);
    u.z = cvt_tf32(v.z); u.w = cvt_tf32(v.w);
    return u;
}

__device__ __forceinline__ void cp_async16(uint32_t smem_dst, const void* gmem_src) {
    asm volatile("cp.async.cg.shared.global [%0], [%1], 16;\n"
                 :: "r"(smem_dst), "l"(gmem_src));
}
__device__ __forceinline__ void cp_commit() {
    asm volatile("cp.async.commit_group;\n");
}
template <int N>
__device__ __forceinline__ void cp_wait() {
    asm volatile("cp.async.wait_group %0;\n" :: "n"(N));
}

__device__ __forceinline__ void mma_tf32(float c[4],
    uint32_t a0, uint32_t a1, uint32_t a2, uint32_t a3,
    uint32_t b0, uint32_t b1)
{
    asm volatile(
        "mma.sync.aligned.m16n8k8.row.col.f32.tf32.tf32.f32 "
        "{%0,%1,%2,%3}, {%4,%5,%6,%7}, {%8,%9}, {%0,%1,%2,%3};\n"
        : "+f"(c[0]), "+f"(c[1]), "+f"(c[2]), "+f"(c[3])
        : "r"(a0), "r"(a1), "r"(a2), "r"(a3), "r"(b0), "r"(b1));
}

// ---------------------------------------------------------------------------
// C[m,n] = sum_k A[m,k]*W[n,k] + bias[n]   (NT, both K-contiguous row-major)
// CTA tile 128(M) x 64(N), 256 threads = 8 warps (4m x 2n), warp 32x32.
// Register-staged double-buffered smem pipeline; 1 barrier per k-tile.
// ---------------------------------------------------------------------------
#define AS_STRIDE 4608   // 128*36
#define BS_STRIDE 2304   // 64*36
__global__ __launch_bounds__(256) void gemm_nt_tc(GArgs args) {
    const int N = HID, K = HID;
    extern __shared__ uint32_t smg[];
    uint32_t* As = smg;                    // [2][128*36]
    uint32_t* Bs = smg + 2 * AS_STRIDE;    // [2][64*36]

    const int z = blockIdx.z;
    const float* __restrict__ A = args.A[z];
    const float* __restrict__ W = args.W[z];
    const float* __restrict__ bias = args.bias[z];
    float* __restrict__ C = args.C[z];
    const bool rnd = args.round_out[z] != 0;

    const int tid = threadIdx.x;
    const int wid = tid >> 5, lane = tid & 31;
    const int g = lane >> 2, tig = lane & 3;
    const int wm = wid >> 1, wn = wid & 1;
    const int m0 = blockIdx.y * 128, n0 = blockIdx.x * 64;

    const int fa_r = tid >> 3, fa_c = (tid & 7) * 4;  // A/B load coords

    float c[2][4][4] = {};
    float4 ra[4], rb[2];

    // prologue: tile 0 -> regs -> smem[0]
    #pragma unroll
    for (int i = 0; i < 4; ++i)
        ra[i] = *(const float4*)&A[(size_t)(m0 + fa_r + i * 32) * K + fa_c];
    #pragma unroll
    for (int i = 0; i < 2; ++i)
        rb[i] = *(const float4*)&W[(size_t)(n0 + fa_r + i * 32) * K + fa_c];
    #pragma unroll
    for (int i = 0; i < 4; ++i)
        *(uint4*)&As[(fa_r + i * 32) * 36 + fa_c] = cvt4(ra[i]);
    #pragma unroll
    for (int i = 0; i < 2; ++i)
        *(uint4*)&Bs[(fa_r + i * 32) * 36 + fa_c] = cvt4(rb[i]);
    __syncthreads();

    #pragma unroll 2
    for (int k0 = 0; k0 < K; k0 += 32) {
        const int buf = (k0 >> 5) & 1;
        const uint32_t* Ac = As + buf * AS_STRIDE;
        const uint32_t* Bc = Bs + buf * BS_STRIDE;
        const bool has_next = (k0 + 32) < K;

        if (has_next) {
            const int k1 = k0 + 32;
            #pragma unroll
            for (int i = 0; i < 4; ++i)
                ra[i] = *(const float4*)&A[(size_t)(m0 + fa_r + i * 32) * K + k1 + fa_c];
            #pragma unroll
            for (int i = 0; i < 2; ++i)
                rb[i] = *(const float4*)&W[(size_t)(n0 + fa_r + i * 32) * K + k1 + fa_c];
        }

        #pragma unroll
        for (int ks = 0; ks < 4; ++ks) {
            const int kc = ks * 8;
            uint32_t a[2][4];
            #pragma unroll
            for (int mt = 0; mt < 2; ++mt) {
                const int row = wm * 32 + mt * 16;
                a[mt][0] = Ac[(row + g    ) * 36 + kc + tig    ];
                a[mt][1] = Ac[(row + g + 8) * 36 + kc + tig    ];
                a[mt][2] = Ac[(row + g    ) * 36 + kc + tig + 4];
                a[mt][3] = Ac[(row + g + 8) * 36 + kc + tig + 4];
            }
            uint32_t b[4][2];
            #pragma unroll
            for (int nt = 0; nt < 4; ++nt) {
                const int col = wn * 32 + nt * 8;
                b[nt][0] = Bc[(col + g) * 36 + kc + tig    ];
                b[nt][1] = Bc[(col + g) * 36 + kc + tig + 4];
            }
            #pragma unroll
            for (int mt = 0; mt < 2; ++mt)
                #pragma unroll
                for (int nt = 0; nt < 4; ++nt)
                    mma_tf32(c[mt][nt], a[mt][0], a[mt][1], a[mt][2], a[mt][3],
                             b[nt][0], b[nt][1]);
        }

        if (has_next) {
            uint32_t* An = As + (buf ^ 1) * AS_STRIDE;
            uint32_t* Bn = Bs + (buf ^ 1) * BS_STRIDE;
            #pragma unroll
            for (int i = 0; i < 4; ++i)
                *(uint4*)&An[(fa_r + i * 32) * 36 + fa_c] = cvt4(ra[i]);
            #pragma unroll
            for (int i = 0; i < 2; ++i)
                *(uint4*)&Bn[(fa_r + i * 32) * 36 + fa_c] = cvt4(rb[i]);
        }
        __syncthreads();
    }

    #pragma unroll
    for (int mt = 0; mt < 2; ++mt) {
        const int row = m0 + wm * 32 + mt * 16 + g;
        #pragma unroll
        for (int nt = 0; nt < 4; ++nt) {
            const int col = n0 + wn * 32 + nt * 8 + 2 * tig;
            const float bx = bias[col], by = bias[col + 1];
            float v0 = c[mt][nt][0] + bx, v1 = c[mt][nt][1] + by;
            float v2 = c[mt][nt][2] + bx, v3 = c[mt][nt][3] + by;
            if (rnd) {
                v0 = __uint_as_float(cvt_tf32(v0));
                v1 = __uint_as_float(cvt_tf32(v1));
                v2 = __uint_as_float(cvt_tf32(v2));
                v3 = __uint_as_float(cvt_tf32(v3));
            }
            *(float2*)&C[(size_t)row * N + col] = make_float2(v0, v1);
            *(float2*)&C[(size_t)(row + 8) * N + col] = make_float2(v2, v3);
        }
    }
}

// ---------------------------------------------------------------------------
// Flash-style causal attention with relative-position terms, tf32 mma.
// CTA: 128 q-rows per (b,h); 256 threads = 8 warps; warp owns 16 q-rows.
// 2 CTAs/SM -> 16 warps/SM (2x the 64-row version). K/V tiles (64 keys)
// are cp.async double-buffered and each serves all 128 q-rows.
// Far/near branch is warp-uniform: dq_tile + rw >= 68 <=> no mask, id==0.
// ---------------------------------------------------------------------------
__global__ __launch_bounds__(256) void attn_tc(
    const float* __restrict__ gq, const float* __restrict__ gk,
    const float* __restrict__ gv, const float* __restrict__ relk,
    const float* __restrict__ relv, float* __restrict__ gctx)
{
    extern __shared__ float sm[];
    float* Qs   = sm;                  // 128*68, reused as Ps after Q frags cached
    float* Ks0  = Qs + 128 * 68;       // [2][64*68]
    float* Vs0  = Ks0 + 2 * 64 * 68;   // [2][64*72]
    float* prel = Vs0 + 2 * 64 * 72;   // [128][6]  (pre-scaled by 0.125 via Q)
    float* nearw = prel + 128 * 6;     // [128][5]

    const int tid = threadIdx.x;
    const int wid = tid >> 5, lane = tid & 31;
    const int g = lane >> 2, tig = lane & 3;
    const int qt = blockIdx.x;
    const int h = blockIdx.y, b = blockIdx.z;
    const int q0 = qt * 128;
    const int rw = wid * 16;           // warp's first q-row (local, 0..112)
    const size_t base = ((size_t)b * LL) * HID + (size_t)h * HD;

    const int fr = tid >> 4, fc = (tid & 15) * 4;   // tile load coords (fr 0..15)

    // Load Q tile (128 rows), pre-scaled by 1/sqrt(HD)=0.125 (exact on tf32)
    #pragma unroll
    for (int i = 0; i < 8; ++i) {
        int r = fr + i * 16;
        float4 v = *(const float4*)&gq[base + (size_t)(q0 + r) * HID + fc];
        v.x *= 0.125f; v.y *= 0.125f; v.z *= 0.125f; v.w *= 0.125f;
        *(float4*)&Qs[r * 68 + fc] = v;
    }
    for (int idx = tid; idx < 128 * 5; idx += 256) nearw[idx] = 0.f;

    // issue cp.async for K/V tile 0 (overlaps prel + Q-frag caching)
    #pragma unroll
    for (int i = 0; i < 4; ++i) {
        int r = fr + i * 16;
        cp_async16((uint32_t)__cvta_generic_to_shared(&Ks0[r * 68 + fc]),
                   &gk[base + (size_t)(r) * HID + fc]);
        cp_async16((uint32_t)__cvta_generic_to_shared(&Vs0[r * 72 + fc]),
                   &gv[base + (size_t)(r) * HID + fc]);
    }
    cp_commit();
    __syncthreads();

    // prel[r][j] = Qscaled[r] . rel_k[j]
    for (int idx = tid; idx < 128 * 6; idx += 256) {
        int r = idx / 6, j = idx % 6;
        float s = 0.f;
        #pragma unroll
        for (int d = 0; d < HD; ++d) s = fmaf(Qs[r * 68 + d], relk[j * HD + d], s);
        prel[r * 6 + j] = s;
    }

    // Cache Q A-fragments in registers (frees Qs smem for P)
    uint32_t qa[8][4];
    #pragma unroll
    for (int k8 = 0; k8 < 8; ++k8) {
        const int kc = k8 * 8;
        qa[k8][0] = fu(Qs[(rw + g    ) * 68 + kc + tig    ]);
        qa[k8][1] = fu(Qs[(rw + g + 8) * 68 + kc + tig    ]);
        qa[k8][2] = fu(Qs[(rw + g    ) * 68 + kc + tig + 4]);
        qa[k8][3] = fu(Qs[(rw + g + 8) * 68 + kc + tig + 4]);
    }

    float m0r = -1e30f, m1r = -1e30f, l0r = 0.f, l1r = 0.f;
    float o[8][4] = {};

    const int KT = 2 * qt + 2;   // key tiles covering rows [0, q0+128)

    for (int kt = 0; kt < KT; ++kt) {
        const int buf = kt & 1;
        float* Ks = Ks0 + buf * (64 * 68);
        float* Vs = Vs0 + buf * (64 * 72);

        // issue next tile into the other buffer, then wait for current
        if (kt + 1 < KT) {
            float* Kn = Ks0 + (buf ^ 1) * (64 * 68);
            float* Vn = Vs0 + (buf ^ 1) * (64 * 72);
            const int kn = (kt + 1) * 64;
            #pragma unroll
            for (int i = 0; i < 4; ++i) {
                int r = fr + i * 16;
                cp_async16((uint32_t)__cvta_generic_to_shared(&Kn[r * 68 + fc]),
                           &gk[base + (size_t)(kn + r) * HID + fc]);
                cp_async16((uint32_t)__cvta_generic_to_shared(&Vn[r * 72 + fc]),
                           &gv[base + (size_t)(kn + r) * HID + fc]);
            }
            cp_commit();
            cp_wait<1>();
        } else {
            cp_wait<0>();
        }
        __syncthreads();   // current tile visible to all warps

        // S = Qscaled @ K^T  (warp: 16 x 64)
        float s[8][4] = {};
        #pragma unroll
        for (int k8 = 0; k8 < 8; ++k8) {
            const int kc = k8 * 8;
            #pragma unroll
            for (int nt = 0; nt < 8; ++nt) {
                uint32_t b0 = fu(Ks[(nt * 8 + g) * 68 + kc + tig    ]);
                uint32_t b1 = fu(Ks[(nt * 8 + g) * 68 + kc + tig + 4]);
                mma_tf32(s[nt], qa[k8][0], qa[k8][1], qa[k8][2], qa[k8][3], b0, b1);
            }
        }

        const int dq = q0 - kt * 64;   // d = dq + rl - col
        const int rl0 = rw + g, rl1 = rw + g + 8;
        const bool warp_far = (dq + rw >= 68);   // all d>=5 for this warp

        // bias + mask
        float rm0 = -1e30f, rm1 = -1e30f;
        if (warp_far) {
            const float p0 = prel[rl0 * 6];
            const float p1 = prel[rl1 * 6];
            #pragma unroll
            for (int nt = 0; nt < 8; ++nt) {
                s[nt][0] += p0; s[nt][1] += p0;
                s[nt][2] += p1; s[nt][3] += p1;
                rm0 = fmaxf(rm0, fmaxf(s[nt][0], s[nt][1]));
                rm1 = fmaxf(rm1, fmaxf(s[nt][2], s[nt][3]));
            }
        } else {
            #pragma unroll
            for (int nt = 0; nt < 8; ++nt) {
                #pragma unroll
                for (int e = 0; e < 4; ++e) {
                    const int rl = (e < 2) ? rl0 : rl1;
                    const int col = nt * 8 + 2 * tig + (e & 1);
                    const int d = dq + rl - col;
                    if (d < 0) s[nt][e] = -1e30f;
                    else {
                        const int id = (d >= 5) ? 0 : (5 - d);
                        s[nt][e] = s[nt][e] + prel[rl * 6 + id];
                    }
                }
                rm0 = fmaxf(rm0, fmaxf(s[nt][0], s[nt][1]));
                rm1 = fmaxf(rm1, fmaxf(s[nt][2], s[nt][3]));
            }
        }
        rm0 = fmaxf(rm0, __shfl_xor_sync(0xffffffffu, rm0, 1));
        rm0 = fmaxf(rm0, __shfl_xor_sync(0xffffffffu, rm0, 2));
        rm1 = fmaxf(rm1, __shfl_xor_sync(0xffffffffu, rm1, 1));
        rm1 = fmaxf(rm1, __shfl_xor_sync(0xffffffffu, rm1, 2));

        const float mn0 = fmaxf(m0r, rm0), mn1 = fmaxf(m1r, rm1);
        const float sc0 = __expf(m0r - mn0), sc1 = __expf(m1r - mn1);
        float ls0 = 0.f, ls1 = 0.f;
        #pragma unroll
        for (int nt = 0; nt < 8; ++nt) {
            s[nt][0] = __expf(s[nt][0] - mn0);
            s[nt][1] = __expf(s[nt][1] - mn0);
            s[nt][2] = __expf(s[nt][2] - mn1);
            s[nt][3] = __expf(s[nt][3] - mn1);
            ls0 += s[nt][0] + s[nt][1];
            ls1 += s[nt][2] + s[nt][3];
        }
        ls0 += __shfl_xor_sync(0xffffffffu, ls0, 1);
        ls0 += __shfl_xor_sync(0xffffffffu, ls0, 2);
        ls1 += __shfl_xor_sync(0xffffffffu, ls1, 1);
        ls1 += __shfl_xor_sync(0xffffffffu, ls1, 2);

        m0r = mn0; m1r = mn1;
        l0r = l0r * sc0 + ls0;
        l1r = l1r * sc1 + ls1;
        #pragma unroll
        for (int dt = 0; dt < 8; ++dt) {
            o[dt][0] *= sc0; o[dt][1] *= sc0;
            o[dt][2] *= sc1; o[dt][3] *= sc1;
        }

        if (!warp_far) {   // near-diag/masked region for this warp's rows
            if (tig == 0) {
                #pragma unroll
                for (int dd = 0; dd < 5; ++dd) {
                    nearw[rl0 * 5 + dd] *= sc0;
                    nearw[rl1 * 5 + dd] *= sc1;
                }
            }
            __syncwarp();
            #pragma unroll
            for (int nt = 0; nt < 8; ++nt) {
                #pragma unroll
                for (int e = 0; e < 4; ++e) {
                    const int rl = (e < 2) ? rl0 : rl1;
                    const int col = nt * 8 + 2 * tig + (e & 1);
                    const int d = dq + rl - col;
                    if (d >= 0 && d < 5) nearw[rl * 5 + d] = s[nt][e];
                }
            }
        }

        // write P into Qs (reused region), tf32-rounded patterns
        #pragma unroll
        for (int nt = 0; nt < 8; ++nt) {
            uint2 p01, p23;
            p01.x = cvt_tf32(s[nt][0]); p01.y = cvt_tf32(s[nt][1]);
            p23.x = cvt_tf32(s[nt][2]); p23.y = cvt_tf32(s[nt][3]);
            *(uint2*)&Qs[rl0 * 68 + nt * 8 + 2 * tig] = p01;
            *(uint2*)&Qs[rl1 * 68 + nt * 8 + 2 * tig] = p23;
        }
        __syncwarp();

        // O += P @ V  (B-frag reads row-major V directly: b0=V[kc+tig][dt*8+g])
        #pragma unroll
        for (int k8 = 0; k8 < 8; ++k8) {
            const int kc = k8 * 8;
            uint32_t pa0 = fu(Qs[rl0 * 68 + kc + tig    ]);
            uint32_t pa1 = fu(Qs[rl1 * 68 + kc + tig    ]);
            uint32_t pa2 = fu(Qs[rl0 * 68 + kc + tig + 4]);
            uint32_t pa3 = fu(Qs[rl1 * 68 + kc + tig + 4]);
            #pragma unroll
            for (int dt = 0; dt < 8; ++dt) {
                uint32_t b0 = fu(Vs[(kc + tig    ) * 72 + dt * 8 + g]);
                uint32_t b1 = fu(Vs[(kc + tig + 4) * 72 + dt * 8 + g]);
                mma_tf32(o[dt], pa0, pa1, pa2, pa3, b0, b1);
            }
        }
        __syncthreads();   // readers of this buffer done before it is refilled
    }

    // Epilogue: rel_v near/far trick + normalize
    const int rl0 = rw + g, rl1 = rw + g + 8;
    const float inv0 = 1.f / l0r, inv1 = 1.f / l1r;
    const float a0 = nearw[rl0*5+0], a1 = nearw[rl0*5+1], a2 = nearw[rl0*5+2],
                a3 = nearw[rl0*5+3], a4 = nearw[rl0*5+4];
    const float b0 = nearw[rl1*5+0], b1 = nearw[rl1*5+1], b2 = nearw[rl1*5+2],
                b3 = nearw[rl1*5+3], b4 = nearw[rl1*5+4];
    const float far0 = l0r - (a0 + a1 + a2 + a3 + a4);
    const float far1 = l1r - (b0 + b1 + b2 + b3 + b4);

    #pragma unroll
    for (int dt = 0; dt < 8; ++dt) {
        const int c = dt * 8 + 2 * tig;
        #pragma unroll
        for (int j = 0; j < 2; ++j) {
            const int cc = c + j;
            const float r5 = relv[5*HD+cc], r4 = relv[4*HD+cc], r3 = relv[3*HD+cc],
                        r2 = relv[2*HD+cc], r1 = relv[1*HD+cc], r0 = relv[cc];
            float e0 = a0*r5 + a1*r4 + a2*r3 + a3*r2 + a4*r1 + far0*r0;
            float e1 = b0*r5 + b1*r4 + b2*r3 + b3*r2 + b4*r1 + far1*r0;
            gctx[base + (size_t)(q0 + rl0) * HID + cc] = (o[dt][j]     + e0) * inv0;
            gctx[base + (size_t)(q0 + rl1) * HID + cc] = (o[dt][2 + j] + e1) * inv1;
        }
    }
}

extern "C" void kernel_launch(void* const* d_in, const int* in_sizes, int n_in,
                              void* d_out, int out_size) {
    (void)in_sizes; (void)n_in; (void)out_size;
    const float* query = (const float*)d_in[0];
    const float* key   = (const float*)d_in[1];
    const float* value = (const float*)d_in[2];
    const float* Wq = (const float*)d_in[3];
    const float* bq = (const float*)d_in[4];
    const float* Wk = (const float*)d_in[5];
    const float* bk = (const float*)d_in[6];
    const float* Wv = (const float*)d_in[7];
    const float* bv = (const float*)d_in[8];
    const float* Wo = (const float*)d_in[9];
    const float* bo = (const float*)d_in[10];
    const float* relk = (const float*)d_in[11];
    const float* relv = (const float*)d_in[12];

    float *pq, *pk, *pv, *pctx;
    cudaGetSymbolAddress((void**)&pq,  g_q);
    cudaGetSymbolAddress((void**)&pk,  g_k);
    cudaGetSymbolAddress((void**)&pv,  g_v);
    cudaGetSymbolAddress((void**)&pctx, g_ctx);

    const int GSMEM = 2 * (AS_STRIDE + BS_STRIDE) * (int)sizeof(uint32_t); // 55296
    cudaFuncSetAttribute(gemm_nt_tc,
                         cudaFuncAttributeMaxDynamicSharedMemorySize, GSMEM);

    // 1) QKV projections (one launch, grid.z = 3) — outputs tf32-pre-rounded
    GArgs qkv;
    qkv.A[0] = query; qkv.W[0] = Wq; qkv.bias[0] = bq; qkv.C[0] = pq; qkv.round_out[0] = 1;
    qkv.A[1] = key;   qkv.W[1] = Wk; qkv.bias[1] = bk; qkv.C[1] = pk; qkv.round_out[1] = 1;
    qkv.A[2] = value; qkv.W[2] = Wv; qkv.bias[2] = bv; qkv.C[2] = pv; qkv.round_out[2] = 1;
    gemm_nt_tc<<<dim3(HID/64, (BB*LL)/128, 3), 256, GSMEM>>>(qkv);

    // 2) attention — 128 q-rows per CTA, 256 threads
    const int SMEM = (128*68 + 2*64*68 + 2*64*72 + 128*6 + 128*5) * (int)sizeof(float);
    cudaFuncSetAttribute(attn_tc,
                         cudaFuncAttributeMaxDynamicSharedMemorySize, SMEM);
    attn_tc<<<dim3(LL/128, HEADS, BB), 256, SMEM>>>(pq, pk, pv, relk, relv, pctx);

    // 3) output projection — exact fp32 output
    GArgs og;
    og.A[0] = pctx; og.W[0] = Wo; og.bias[0] = bo; og.C[0] = (float*)d_out; og.round_out[0] = 0;
    og.A[1] = og.A[0]; og.W[1] = og.W[0]; og.bias[1] = og.bias[0]; og.C[1] = og.C[0]; og.round_out[1] = 0;
    og.A[2] = og.A[0]; og.W[2] = og.W[0]; og.bias[2] = og.bias[0]; og.C[2] = og.C[0]; og.round_out[2] = 0;
    gemm_nt_tc<<<dim3(HID/64, (BB*LL)/128, 1), 256, GSMEM>>>(og);
}

// round 12
// speedup vs baseline: 1.0455x; 1.0455x over previous
#include <cuda_runtime.h>
#include <math.h>
#include <stdint.h>

#define BB 4
#define LL 1024
#define HID 512
#define HEADS 8
#define HD 64

// Scratch (device globals: allocation-free)
__device__ float g_q[BB*LL*HID];
__device__ float g_k[BB*LL*HID];
__device__ float g_v[BB*LL*HID];
__device__ float g_ctx[BB*LL*HID];

struct GArgs {
    const float* A[3];
    const float* W[3];
    const float* bias[3];
    float* C[3];
    int round_out[3];   // 1: store tf32-rounded C (for q/k/v scratch)
};

// tf32 round (rna) -> 32-bit pattern in a b32 register
__device__ __forceinline__ uint32_t cvt_tf32(float x) {
    uint32_t r;
    asm("cvt.rna.tf32.f32 %0, %1;" : "=r"(r) : "f"(x));
    return r;
}
__device__ __forceinline__ uint32_t fu(float x) { return __float_as_uint(x); }
__device__ __forceinline__ uint4 cvt4(float4 v) {
    uint4 u;
    u.x = cvt_tf32(v.x); u.y = cvt_tf32(v.y);
    u.z = cvt_tf32(v.z); u.w = cvt_tf32(v.w);
    return u;
}

__device__ __forceinline__ void cp_async16(uint32_t smem_dst, const void* gmem_src) {
    asm volatile("cp.async.cg.shared.global [%0], [%1], 16;\n"
                 :: "r"(smem_dst), "l"(gmem_src));
}
__device__ __forceinline__ void cp_commit() {
    asm volatile("cp.async.commit_group;\n");
}
template <int N>
__device__ __forceinline__ void cp_wait() {
    asm volatile("cp.async.wait_group %0;\n" :: "n"(N));
}

__device__ __forceinline__ void mma_tf32(float c[4],
    uint32_t a0, uint32_t a1, uint32_t a2, uint32_t a3,
    uint32_t b0, uint32_t b1)
{
    asm volatile(
        "mma.sync.aligned.m16n8k8.row.col.f32.tf32.tf32.f32 "
        "{%0,%1,%2,%3}, {%4,%5,%6,%7}, {%8,%9}, {%0,%1,%2,%3};\n"
        : "+f"(c[0]), "+f"(c[1]), "+f"(c[2]), "+f"(c[3])
        : "r"(a0), "r"(a1), "r"(a2), "r"(a3), "r"(b0), "r"(b1));
}

// ---------------------------------------------------------------------------
// C[m,n] = sum_k A[m,k]*W[n,k] + bias[n]   (NT, both K-contiguous row-major)
// CTA tile 128(M) x 64(N), 256 threads = 8 warps (4m x 2n), warp 32x32.
// Register-staged double-buffered smem pipeline; 1 barrier per k-tile.
// ---------------------------------------------------------------------------
#define AS_STRIDE 4608   // 128*36
#define BS_STRIDE 2304   // 64*36
__global__ __launch_bounds__(256) void gemm_nt_tc(GArgs args) {
    const int N = HID, K = HID;
    extern __shared__ uint32_t smg[];
    uint32_t* As = smg;                    // [2][128*36]
    uint32_t* Bs = smg + 2 * AS_STRIDE;    // [2][64*36]

    const int z = blockIdx.z;
    const float* __restrict__ A = args.A[z];
    const float* __restrict__ W = args.W[z];
    const float* __restrict__ bias = args.bias[z];
    float* __restrict__ C = args.C[z];
    const bool rnd = args.round_out[z] != 0;

    const int tid = threadIdx.x;
    const int wid = tid >> 5, lane = tid & 31;
    const int g = lane >> 2, tig = lane & 3;
    const int wm = wid >> 1, wn = wid & 1;
    const int m0 = blockIdx.y * 128, n0 = blockIdx.x * 64;

    const int fa_r = tid >> 3, fa_c = (tid & 7) * 4;  // A/B load coords

    float c[2][4][4] = {};
    float4 ra[4], rb[2];

    // prologue: tile 0 -> regs -> smem[0]
    #pragma unroll
    for (int i = 0; i < 4; ++i)
        ra[i] = *(const float4*)&A[(size_t)(m0 + fa_r + i * 32) * K + fa_c];
    #pragma unroll
    for (int i = 0; i < 2; ++i)
        rb[i] = *(const float4*)&W[(size_t)(n0 + fa_r + i * 32) * K + fa_c];
    #pragma unroll
    for (int i = 0; i < 4; ++i)
        *(uint4*)&As[(fa_r + i * 32) * 36 + fa_c] = cvt4(ra[i]);
    #pragma unroll
    for (int i = 0; i < 2; ++i)
        *(uint4*)&Bs[(fa_r + i * 32) * 36 + fa_c] = cvt4(rb[i]);
    __syncthreads();

    #pragma unroll 2
    for (int k0 = 0; k0 < K; k0 += 32) {
        const int buf = (k0 >> 5) & 1;
        const uint32_t* Ac = As + buf * AS_STRIDE;
        const uint32_t* Bc = Bs + buf * BS_STRIDE;
        const bool has_next = (k0 + 32) < K;

        if (has_next) {
            const int k1 = k0 + 32;
            #pragma unroll
            for (int i = 0; i < 4; ++i)
                ra[i] = *(const float4*)&A[(size_t)(m0 + fa_r + i * 32) * K + k1 + fa_c];
            #pragma unroll
            for (int i = 0; i < 2; ++i)
                rb[i] = *(const float4*)&W[(size_t)(n0 + fa_r + i * 32) * K + k1 + fa_c];
        }

        #pragma unroll
        for (int ks = 0; ks < 4; ++ks) {
            const int kc = ks * 8;
            uint32_t a[2][4];
            #pragma unroll
            for (int mt = 0; mt < 2; ++mt) {
                const int row = wm * 32 + mt * 16;
                a[mt][0] = Ac[(row + g    ) * 36 + kc + tig    ];
                a[mt][1] = Ac[(row + g + 8) * 36 + kc + tig    ];
                a[mt][2] = Ac[(row + g    ) * 36 + kc + tig + 4];
                a[mt][3] = Ac[(row + g + 8) * 36 + kc + tig + 4];
            }
            uint32_t b[4][2];
            #pragma unroll
            for (int nt = 0; nt < 4; ++nt) {
                const int col = wn * 32 + nt * 8;
                b[nt][0] = Bc[(col + g) * 36 + kc + tig    ];
                b[nt][1] = Bc[(col + g) * 36 + kc + tig + 4];
            }
            #pragma unroll
            for (int mt = 0; mt < 2; ++mt)
                #pragma unroll
                for (int nt = 0; nt < 4; ++nt)
                    mma_tf32(c[mt][nt], a[mt][0], a[mt][1], a[mt][2], a[mt][3],
                             b[nt][0], b[nt][1]);
        }

        if (has_next) {
            uint32_t* An = As + (buf ^ 1) * AS_STRIDE;
            uint32_t* Bn = Bs + (buf ^ 1) * BS_STRIDE;
            #pragma unroll
            for (int i = 0; i < 4; ++i)
                *(uint4*)&An[(fa_r + i * 32) * 36 + fa_c] = cvt4(ra[i]);
            #pragma unroll
            for (int i = 0; i < 2; ++i)
                *(uint4*)&Bn[(fa_r + i * 32) * 36 + fa_c] = cvt4(rb[i]);
        }
        __syncthreads();
    }

    #pragma unroll
    for (int mt = 0; mt < 2; ++mt) {
        const int row = m0 + wm * 32 + mt * 16 + g;
        #pragma unroll
        for (int nt = 0; nt < 4; ++nt) {
            const int col = n0 + wn * 32 + nt * 8 + 2 * tig;
            const float bx = bias[col], by = bias[col + 1];
            float v0 = c[mt][nt][0] + bx, v1 = c[mt][nt][1] + by;
            float v2 = c[mt][nt][2] + bx, v3 = c[mt][nt][3] + by;
            if (rnd) {
                v0 = __uint_as_float(cvt_tf32(v0));
                v1 = __uint_as_float(cvt_tf32(v1));
                v2 = __uint_as_float(cvt_tf32(v2));
                v3 = __uint_as_float(cvt_tf32(v3));
            }
            *(float2*)&C[(size_t)row * N + col] = make_float2(v0, v1);
            *(float2*)&C[(size_t)(row + 8) * N + col] = make_float2(v2, v3);
        }
    }
}

// ---------------------------------------------------------------------------
// Flash-style causal attention with relative-position terms, tf32 mma.
// CTA: 64 q-rows per (b,h); 128 threads = 4 warps; warp owns 16 q-rows.
// Q/K/V arrive pre-rounded to tf32 (GEMM epilogue), so no cvt on load.
// K/V: cp.async double-buffered tiles; ONE __syncthreads per kt-iteration
// (top barrier guards both load-visibility and buffer reuse; next-tile
// cp.async issued after it, waited at the top of the next iteration).
// ---------------------------------------------------------------------------
__global__ __launch_bounds__(128) void attn_tc(
    const float* __restrict__ gq, const float* __restrict__ gk,
    const float* __restrict__ gv, const float* __restrict__ relk,
    const float* __restrict__ relv, float* __restrict__ gctx)
{
    extern __shared__ float sm[];
    float* Qs   = sm;                  // 64*68, reused as Ps after Q frags cached
    float* Ks0  = Qs + 64 * 68;        // [2][64*68]
    float* Vs0  = Ks0 + 2 * 64 * 68;   // [2][64*72]
    float* prel = Vs0 + 2 * 64 * 72;   // [64][6]  (pre-scaled by 0.125 via Q)
    float* nearw = prel + 64 * 6;      // [64][5]

    const int tid = threadIdx.x;
    const int wid = tid >> 5, lane = tid & 31;
    const int g = lane >> 2, tig = lane & 3;
    const int qt = blockIdx.x;
    const int h = blockIdx.y, b = blockIdx.z;
    const int q0 = qt * 64;
    const int rw = wid * 16;           // warp's first q-row (local)
    const size_t base = ((size_t)b * LL) * HID + (size_t)h * HD;

    const int fr = tid >> 4, fc = (tid & 15) * 4;   // K/V tile load coords

    // Load Q tile, pre-scaled by 1/sqrt(HD)=0.125 (exact on tf32 values)
    #pragma unroll
    for (int i = 0; i < 8; ++i) {
        int r = fr + i * 8;
        float4 v = *(const float4*)&gq[base + (size_t)(q0 + r) * HID + fc];
        v.x *= 0.125f; v.y *= 0.125f; v.z *= 0.125f; v.w *= 0.125f;
        *(float4*)&Qs[r * 68 + fc] = v;
    }
    for (int idx = tid; idx < 64 * 5; idx += 128) nearw[idx] = 0.f;

    // issue cp.async for K/V tile 0 (overlaps prel + Q-frag caching)
    {
        #pragma unroll
        for (int i = 0; i < 8; ++i) {
            int r = fr + i * 8;
            cp_async16((uint32_t)__cvta_generic_to_shared(&Ks0[r * 68 + fc]),
                       &gk[base + (size_t)(r) * HID + fc]);
            cp_async16((uint32_t)__cvta_generic_to_shared(&Vs0[r * 72 + fc]),
                       &gv[base + (size_t)(r) * HID + fc]);
        }
        cp_commit();
    }
    __syncthreads();

    // prel[r][j] = Qscaled[r] . rel_k[j]  (= 0.125 * Q.rel_k exactly)
    for (int idx = tid; idx < 64 * 6; idx += 128) {
        int r = idx / 6, j = idx % 6;
        float s = 0.f;
        #pragma unroll
        for (int d = 0; d < HD; ++d) s = fmaf(Qs[r * 68 + d], relk[j * HD + d], s);
        prel[r * 6 + j] = s;
    }

    // Cache Q A-fragments in registers (frees Qs smem for P)
    uint32_t qa[8][4];
    #pragma unroll
    for (int k8 = 0; k8 < 8; ++k8) {
        const int kc = k8 * 8;
        qa[k8][0] = fu(Qs[(rw + g    ) * 68 + kc + tig    ]);
        qa[k8][1] = fu(Qs[(rw + g + 8) * 68 + kc + tig    ]);
        qa[k8][2] = fu(Qs[(rw + g    ) * 68 + kc + tig + 4]);
        qa[k8][3] = fu(Qs[(rw + g + 8) * 68 + kc + tig + 4]);
    }

    float m0r = -1e30f, m1r = -1e30f, l0r = 0.f, l1r = 0.f;
    float o[8][4] = {};

    for (int kt = 0; kt <= qt; ++kt) {
        const int buf = kt & 1;
        float* Ks = Ks0 + buf * (64 * 68);
        float* Vs = Vs0 + buf * (64 * 72);

        // current tile's group is the only one outstanding; complete it,
        // then one barrier gives (a) all threads' loads visible and
        // (b) buffer buf^1's readers from iteration kt-1 all finished.
        cp_wait<0>();
        __syncthreads();

        // issue next tile into buf^1 (safe after the barrier above);
        // it stays in flight until the top of the next iteration.
        if (kt < qt) {
            float* Kn = Ks0 + (buf ^ 1) * (64 * 68);
            float* Vn = Vs0 + (buf ^ 1) * (64 * 72);
            const int kn = (kt + 1) * 64;
            #pragma unroll
            for (int i = 0; i < 8; ++i) {
                int r = fr + i * 8;
                cp_async16((uint32_t)__cvta_generic_to_shared(&Kn[r * 68 + fc]),
                           &gk[base + (size_t)(kn + r) * HID + fc]);
                cp_async16((uint32_t)__cvta_generic_to_shared(&Vn[r * 72 + fc]),
                           &gv[base + (size_t)(kn + r) * HID + fc]);
            }
            cp_commit();
        }

        // S = Qscaled @ K^T  (warp: 16 x 64)
        float s[8][4] = {};
        #pragma unroll
        for (int k8 = 0; k8 < 8; ++k8) {
            const int kc = k8 * 8;
            #pragma unroll
            for (int nt = 0; nt < 8; ++nt) {
                uint32_t b0 = fu(Ks[(nt * 8 + g) * 68 + kc + tig    ]);
                uint32_t b1 = fu(Ks[(nt * 8 + g) * 68 + kc + tig + 4]);
                mma_tf32(s[nt], qa[k8][0], qa[k8][1], qa[k8][2], qa[k8][3], b0, b1);
            }
        }

        const int dq = (qt - kt) * 64;
        const bool neardiag = (dq <= 64);
        const int rl0 = rw + g, rl1 = rw + g + 8;

        // bias + mask
        float rm0 = -1e30f, rm1 = -1e30f;
        #pragma unroll
        for (int nt = 0; nt < 8; ++nt) {
            #pragma unroll
            for (int e = 0; e < 4; ++e) {
                const int rl = (e < 2) ? rl0 : rl1;
                const int col = nt * 8 + 2 * tig + (e & 1);
                const int d = dq + rl - col;
                if (d < 0) s[nt][e] = -1e30f;
                else {
                    const int id = (d >= 5) ? 0 : (5 - d);
                    s[nt][e] = s[nt][e] + prel[rl * 6 + id];
                }
            }
            rm0 = fmaxf(rm0, fmaxf(s[nt][0], s[nt][1]));
            rm1 = fmaxf(rm1, fmaxf(s[nt][2], s[nt][3]));
        }
        rm0 = fmaxf(rm0, __shfl_xor_sync(0xffffffffu, rm0, 1));
        rm0 = fmaxf(rm0, __shfl_xor_sync(0xffffffffu, rm0, 2));
        rm1 = fmaxf(rm1, __shfl_xor_sync(0xffffffffu, rm1, 1));
        rm1 = fmaxf(rm1, __shfl_xor_sync(0xffffffffu, rm1, 2));

        const float mn0 = fmaxf(m0r, rm0), mn1 = fmaxf(m1r, rm1);
        const float sc0 = __expf(m0r - mn0), sc1 = __expf(m1r - mn1);
        float ls0 = 0.f, ls1 = 0.f;
        #pragma unroll
        for (int nt = 0; nt < 8; ++nt) {
            s[nt][0] = __expf(s[nt][0] - mn0);
            s[nt][1] = __expf(s[nt][1] - mn0);
            s[nt][2] = __expf(s[nt][2] - mn1);
            s[nt][3] = __expf(s[nt][3] - mn1);
            ls0 += s[nt][0] + s[nt][1];
            ls1 += s[nt][2] + s[nt][3];
        }
        ls0 += __shfl_xor_sync(0xffffffffu, ls0, 1);
        ls0 += __shfl_xor_sync(0xffffffffu, ls0, 2);
        ls1 += __shfl_xor_sync(0xffffffffu, ls1, 1);
        ls1 += __shfl_xor_sync(0xffffffffu, ls1, 2);

        m0r = mn0; m1r = mn1;
        l0r = l0r * sc0 + ls0;
        l1r = l1r * sc1 + ls1;
        #pragma unroll
        for (int dt = 0; dt < 8; ++dt) {
            o[dt][0] *= sc0; o[dt][1] *= sc0;
            o[dt][2] *= sc1; o[dt][3] *= sc1;
        }

        if (neardiag) {
            if (tig == 0) {
                #pragma unroll
                for (int dd = 0; dd < 5; ++dd) {
                    nearw[rl0 * 5 + dd] *= sc0;
                    nearw[rl1 * 5 + dd] *= sc1;
                }
            }
            __syncwarp();
            #pragma unroll
            for (int nt = 0; nt < 8; ++nt) {
                #pragma unroll
                for (int e = 0; e < 4; ++e) {
                    const int rl = (e < 2) ? rl0 : rl1;
                    const int col = nt * 8 + 2 * tig + (e & 1);
                    const int d = dq + rl - col;
                    if (d >= 0 && d < 5) nearw[rl * 5 + d] = s[nt][e];
                }
            }
        }

        // write P into Qs (reused region), tf32-rounded patterns
        #pragma unroll
        for (int nt = 0; nt < 8; ++nt) {
            uint2 p01, p23;
            p01.x = cvt_tf32(s[nt][0]); p01.y = cvt_tf32(s[nt][1]);
            p23.x = cvt_tf32(s[nt][2]); p23.y = cvt_tf32(s[nt][3]);
            *(uint2*)&Qs[rl0 * 68 + nt * 8 + 2 * tig] = p01;
            *(uint2*)&Qs[rl1 * 68 + nt * 8 + 2 * tig] = p23;
        }
        __syncwarp();

        // O += P @ V  (B-frag reads row-major V directly: b0=V[kc+tig][dt*8+g])
        #pragma unroll
        for (int k8 = 0; k8 < 8; ++k8) {
            const int kc = k8 * 8;
            uint32_t pa0 = fu(Qs[rl0 * 68 + kc + tig    ]);
            uint32_t pa1 = fu(Qs[rl1 * 68 + kc + tig    ]);
            uint32_t pa2 = fu(Qs[rl0 * 68 + kc + tig + 4]);
            uint32_t pa3 = fu(Qs[rl1 * 68 + kc + tig + 4]);
            #pragma unroll
            for (int dt = 0; dt < 8; ++dt) {
                uint32_t b0 = fu(Vs[(kc + tig    ) * 72 + dt * 8 + g]);
                uint32_t b1 = fu(Vs[(kc + tig + 4) * 72 + dt * 8 + g]);
                mma_tf32(o[dt], pa0, pa1, pa2, pa3, b0, b1);
            }
        }
        // no trailing barrier: next iteration's top barrier guards reuse
    }
    __syncwarp();   // order tig==0 nearw writes before cross-lane epilogue reads

    // Epilogue: rel_v near/far trick + normalize
    const int rl0 = rw + g, rl1 = rw + g + 8;
    const float inv0 = 1.f / l0r, inv1 = 1.f / l1r;
    const float a0 = nearw[rl0*5+0], a1 = nearw[rl0*5+1], a2 = nearw[rl0*5+2],
                a3 = nearw[rl0*5+3], a4 = nearw[rl0*5+4];
    const float b0 = nearw[rl1*5+0], b1 = nearw[rl1*5+1], b2 = nearw[rl1*5+2],
                b3 = nearw[rl1*5+3], b4 = nearw[rl1*5+4];
    const float far0 = l0r - (a0 + a1 + a2 + a3 + a4);
    const float far1 = l1r - (b0 + b1 + b2 + b3 + b4);

    #pragma unroll
    for (int dt = 0; dt < 8; ++dt) {
        const int c = dt * 8 + 2 * tig;
        #pragma unroll
        for (int j = 0; j < 2; ++j) {
            const int cc = c + j;
            const float r5 = relv[5*HD+cc], r4 = relv[4*HD+cc], r3 = relv[3*HD+cc],
                        r2 = relv[2*HD+cc], r1 = relv[1*HD+cc], r0 = relv[cc];
            float e0 = a0*r5 + a1*r4 + a2*r3 + a3*r2 + a4*r1 + far0*r0;
            float e1 = b0*r5 + b1*r4 + b2*r3 + b3*r2 + b4*r1 + far1*r0;
            gctx[base + (size_t)(q0 + rl0) * HID + cc] = (o[dt][j]     + e0) * inv0;
            gctx[base + (size_t)(q0 + rl1) * HID + cc] = (o[dt][2 + j] + e1) * inv1;
        }
    }
}

extern "C" void kernel_launch(void* const* d_in, const int* in_sizes, int n_in,
                              void* d_out, int out_size) {
    (void)in_sizes; (void)n_in; (void)out_size;
    const float* query = (const float*)d_in[0];
    const float* key   = (const float*)d_in[1];
    const float* value = (const float*)d_in[2];
    const float* Wq = (const float*)d_in[3];
    const float* bq = (const float*)d_in[4];
    const float* Wk = (const float*)d_in[5];
    const float* bk = (const float*)d_in[6];
    const float* Wv = (const float*)d_in[7];
    const float* bv = (const float*)d_in[8];
    const float* Wo = (const float*)d_in[9];
    const float* bo = (const float*)d_in[10];
    const float* relk = (const float*)d_in[11];
    const float* relv = (const float*)d_in[12];

    float *pq, *pk, *pv, *pctx;
    cudaGetSymbolAddress((void**)&pq,  g_q);
    cudaGetSymbolAddress((void**)&pk,  g_k);
    cudaGetSymbolAddress((void**)&pv,  g_v);
    cudaGetSymbolAddress((void**)&pctx, g_ctx);

    const int GSMEM = 2 * (AS_STRIDE + BS_STRIDE) * (int)sizeof(uint32_t); // 55296
    cudaFuncSetAttribute(gemm_nt_tc,
                         cudaFuncAttributeMaxDynamicSharedMemorySize, GSMEM);

    // 1) QKV projections (one launch, grid.z = 3) — outputs tf32-pre-rounded
    GArgs qkv;
    qkv.A[0] = query; qkv.W[0] = Wq; qkv.bias[0] = bq; qkv.C[0] = pq; qkv.round_out[0] = 1;
    qkv.A[1] = key;   qkv.W[1] = Wk; qkv.bias[1] = bk; qkv.C[1] = pk; qkv.round_out[1] = 1;
    qkv.A[2] = value; qkv.W[2] = Wv; qkv.bias[2] = bv; qkv.C[2] = pv; qkv.round_out[2] = 1;
    gemm_nt_tc<<<dim3(HID/64, (BB*LL)/128, 3), 256, GSMEM>>>(qkv);

    // 2) attention — 64 q-rows per CTA, 128 threads (R8 config)
    const int SMEM = (64*68 + 2*64*68 + 2*64*72 + 64*6 + 64*5) * (int)sizeof(float);
    cudaFuncSetAttribute(attn_tc,
                         cudaFuncAttributeMaxDynamicSharedMemorySize, SMEM);
    attn_tc<<<dim3(LL/64, HEADS, BB), 128, SMEM>>>(pq, pk, pv, relk, relv, pctx);

    // 3) output projection — exact fp32 output
    GArgs og;
    og.A[0] = pctx; og.W[0] = Wo; og.bias[0] = bo; og.C[0] = (float*)d_out; og.round_out[0] = 0;
    og.A[1] = og.A[0]; og.W[1] = og.W[0]; og.bias[1] = og.bias[0]; og.C[1] = og.C[0]; og.round_out[1] = 0;
    og.A[2] = og.A[0]; og.W[2] = og.W[0]; og.bias[2] = og.bias[0]; og.C[2] = og.C[0]; og.round_out[2] = 0;
    gemm_nt_tc<<<dim3(HID/64, (BB*LL)/128, 1), 256, GSMEM>>>(og);
}

// round 13
// speedup vs baseline: 1.0701x; 1.0235x over previous
#include <cuda_runtime.h>
#include <math.h>
#include <stdint.h>

#define BB 4
#define LL 1024
#define HID 512
#define HEADS 8
#define HD 64

// Scratch (device globals: allocation-free)
__device__ float g_q[BB*LL*HID];
__device__ float g_k[BB*LL*HID];
__device__ float g_v[BB*LL*HID];
__device__ float g_ctx[BB*LL*HID];

struct GArgs {
    const float* A[3];
    const float* W[3];
    const float* bias[3];
    float* C[3];
    int round_out[3];   // 1: store tf32-rounded C (for q/k/v scratch)
    int perm_out[3];    // 1: permute columns within 8-groups (K scratch only)
};

// tf32 round (rna) -> 32-bit pattern in a b32 register
__device__ __forceinline__ uint32_t cvt_tf32(float x) {
    uint32_t r;
    asm("cvt.rna.tf32.f32 %0, %1;" : "=r"(r) : "f"(x));
    return r;
}
__device__ __forceinline__ uint32_t fu(float x) { return __float_as_uint(x); }
__device__ __forceinline__ uint4 cvt4(float4 v) {
    uint4 u;
    u.x = cvt_tf32(v.x); u.y = cvt_tf32(v.y);
    u.z = cvt_tf32(v.z); u.w = cvt_tf32(v.w);
    return u;
}

// column permutation within each 8-group: m -> 2*(m&3) + ((m>>2)&1)
__device__ __forceinline__ int perm8(int c) {
    return (c & ~7) | ((2 * (c & 3)) | ((c >> 2) & 1));
}

__device__ __forceinline__ void cp_async16(uint32_t smem_dst, const void* gmem_src) {
    asm volatile("cp.async.cg.shared.global [%0], [%1], 16;\n"
                 :: "r"(smem_dst), "l"(gmem_src));
}
__device__ __forceinline__ void cp_commit() {
    asm volatile("cp.async.commit_group;\n");
}
template <int N>
__device__ __forceinline__ void cp_wait() {
    asm volatile("cp.async.wait_group %0;\n" :: "n"(N));
}

__device__ __forceinline__ void mma_tf32(float c[4],
    uint32_t a0, uint32_t a1, uint32_t a2, uint32_t a3,
    uint32_t b0, uint32_t b1)
{
    asm volatile(
        "mma.sync.aligned.m16n8k8.row.col.f32.tf32.tf32.f32 "
        "{%0,%1,%2,%3}, {%4,%5,%6,%7}, {%8,%9}, {%0,%1,%2,%3};\n"
        : "+f"(c[0]), "+f"(c[1]), "+f"(c[2]), "+f"(c[3])
        : "r"(a0), "r"(a1), "r"(a2), "r"(a3), "r"(b0), "r"(b1));
}

// ---------------------------------------------------------------------------
// C[m,n] = sum_k A[m,k]*W[n,k] + bias[n]   (NT, both K-contiguous row-major)
// CTA tile 128(M) x 64(N), 256 threads = 8 warps (4m x 2n), warp 32x32.
// Register-staged double-buffered smem pipeline; 1 barrier per k-tile.
// ---------------------------------------------------------------------------
#define AS_STRIDE 4608   // 128*36
#define BS_STRIDE 2304   // 64*36
__global__ __launch_bounds__(256) void gemm_nt_tc(GArgs args) {
    const int N = HID, K = HID;
    extern __shared__ uint32_t smg[];
    uint32_t* As = smg;                    // [2][128*36]
    uint32_t* Bs = smg + 2 * AS_STRIDE;    // [2][64*36]

    const int z = blockIdx.z;
    const float* __restrict__ A = args.A[z];
    const float* __restrict__ W = args.W[z];
    const float* __restrict__ bias = args.bias[z];
    float* __restrict__ C = args.C[z];
    const bool rnd = args.round_out[z] != 0;
    const bool prm = args.perm_out[z] != 0;

    const int tid = threadIdx.x;
    const int wid = tid >> 5, lane = tid & 31;
    const int g = lane >> 2, tig = lane & 3;
    const int wm = wid >> 1, wn = wid & 1;
    const int m0 = blockIdx.y * 128, n0 = blockIdx.x * 64;

    const int fa_r = tid >> 3, fa_c = (tid & 7) * 4;  // A/B load coords

    float c[2][4][4] = {};
    float4 ra[4], rb[2];

    // prologue: tile 0 -> regs -> smem[0]
    #pragma unroll
    for (int i = 0; i < 4; ++i)
        ra[i] = *(const float4*)&A[(size_t)(m0 + fa_r + i * 32) * K + fa_c];
    #pragma unroll
    for (int i = 0; i < 2; ++i)
        rb[i] = *(const float4*)&W[(size_t)(n0 + fa_r + i * 32) * K + fa_c];
    #pragma unroll
    for (int i = 0; i < 4; ++i)
        *(uint4*)&As[(fa_r + i * 32) * 36 + fa_c] = cvt4(ra[i]);
    #pragma unroll
    for (int i = 0; i < 2; ++i)
        *(uint4*)&Bs[(fa_r + i * 32) * 36 + fa_c] = cvt4(rb[i]);
    __syncthreads();

    #pragma unroll 2
    for (int k0 = 0; k0 < K; k0 += 32) {
        const int buf = (k0 >> 5) & 1;
        const uint32_t* Ac = As + buf * AS_STRIDE;
        const uint32_t* Bc = Bs + buf * BS_STRIDE;
        const bool has_next = (k0 + 32) < K;

        if (has_next) {
            const int k1 = k0 + 32;
            #pragma unroll
            for (int i = 0; i < 4; ++i)
                ra[i] = *(const float4*)&A[(size_t)(m0 + fa_r + i * 32) * K + k1 + fa_c];
            #pragma unroll
            for (int i = 0; i < 2; ++i)
                rb[i] = *(const float4*)&W[(size_t)(n0 + fa_r + i * 32) * K + k1 + fa_c];
        }

        #pragma unroll
        for (int ks = 0; ks < 4; ++ks) {
            const int kc = ks * 8;
            uint32_t a[2][4];
            #pragma unroll
            for (int mt = 0; mt < 2; ++mt) {
                const int row = wm * 32 + mt * 16;
                a[mt][0] = Ac[(row + g    ) * 36 + kc + tig    ];
                a[mt][1] = Ac[(row + g + 8) * 36 + kc + tig    ];
                a[mt][2] = Ac[(row + g    ) * 36 + kc + tig + 4];
                a[mt][3] = Ac[(row + g + 8) * 36 + kc + tig + 4];
            }
            uint32_t b[4][2];
            #pragma unroll
            for (int nt = 0; nt < 4; ++nt) {
                const int col = wn * 32 + nt * 8;
                b[nt][0] = Bc[(col + g) * 36 + kc + tig    ];
                b[nt][1] = Bc[(col + g) * 36 + kc + tig + 4];
            }
            #pragma unroll
            for (int mt = 0; mt < 2; ++mt)
                #pragma unroll
                for (int nt = 0; nt < 4; ++nt)
                    mma_tf32(c[mt][nt], a[mt][0], a[mt][1], a[mt][2], a[mt][3],
                             b[nt][0], b[nt][1]);
        }

        if (has_next) {
            uint32_t* An = As + (buf ^ 1) * AS_STRIDE;
            uint32_t* Bn = Bs + (buf ^ 1) * BS_STRIDE;
            #pragma unroll
            for (int i = 0; i < 4; ++i)
                *(uint4*)&An[(fa_r + i * 32) * 36 + fa_c] = cvt4(ra[i]);
            #pragma unroll
            for (int i = 0; i < 2; ++i)
                *(uint4*)&Bn[(fa_r + i * 32) * 36 + fa_c] = cvt4(rb[i]);
        }
        __syncthreads();
    }

    #pragma unroll
    for (int mt = 0; mt < 2; ++mt) {
        const int row = m0 + wm * 32 + mt * 16 + g;
        #pragma unroll
        for (int nt = 0; nt < 4; ++nt) {
            const int col = n0 + wn * 32 + nt * 8 + 2 * tig;
            const float bx = bias[col], by = bias[col + 1];
            float v0 = c[mt][nt][0] + bx, v1 = c[mt][nt][1] + by;
            float v2 = c[mt][nt][2] + bx, v3 = c[mt][nt][3] + by;
            if (rnd) {
                v0 = __uint_as_float(cvt_tf32(v0));
                v1 = __uint_as_float(cvt_tf32(v1));
                v2 = __uint_as_float(cvt_tf32(v2));
                v3 = __uint_as_float(cvt_tf32(v3));
            }
            if (prm) {   // K scratch: permuted columns (scalar stores)
                const int p0c = perm8(col);
                const int p1c = perm8(col + 1);
                C[(size_t)row * N + p0c] = v0;
                C[(size_t)row * N + p1c] = v1;
                C[(size_t)(row + 8) * N + p0c] = v2;
                C[(size_t)(row + 8) * N + p1c] = v3;
            } else {
                *(float2*)&C[(size_t)row * N + col] = make_float2(v0, v1);
                *(float2*)&C[(size_t)(row + 8) * N + col] = make_float2(v2, v3);
            }
        }
    }
}

// ---------------------------------------------------------------------------
// Flash-style causal attention with relative-position terms, tf32 mma.
// CTA: 64 q-rows per (b,h); 128 threads = 4 warps; warp owns 16 q-rows.
// Q/K/V arrive pre-rounded to tf32 (GEMM epilogue), so no cvt on load.
// K is stored column-permuted (perm8) so both B-frag k-elements of each
// thread are adjacent -> one LDS.64 per fragment (stride 72: conflict-free).
// K/V cp.async double-buffered; one __syncthreads per kt-iteration.
// ---------------------------------------------------------------------------
__global__ __launch_bounds__(128) void attn_tc(
    const float* __restrict__ gq, const float* __restrict__ gk,
    const float* __restrict__ gv, const float* __restrict__ relk,
    const float* __restrict__ relv, float* __restrict__ gctx)
{
    extern __shared__ float sm[];
    float* Qs   = sm;                  // 64*68, reused as Ps after Q frags cached
    float* Ks0  = Qs + 64 * 68;        // [2][64*72]  (permuted columns)
    float* Vs0  = Ks0 + 2 * 64 * 72;   // [2][64*72]
    float* prel = Vs0 + 2 * 64 * 72;   // [64][6]  (pre-scaled by 0.125 via Q)
    float* nearw = prel + 64 * 6;      // [64][5]

    const int tid = threadIdx.x;
    const int wid = tid >> 5, lane = tid & 31;
    const int g = lane >> 2, tig = lane & 3;
    const int qt = blockIdx.x;
    const int h = blockIdx.y, b = blockIdx.z;
    const int q0 = qt * 64;
    const int rw = wid * 16;           // warp's first q-row (local)
    const size_t base = ((size_t)b * LL) * HID + (size_t)h * HD;

    const int fr = tid >> 4, fc = (tid & 15) * 4;   // K/V tile load coords

    // Load Q tile, pre-scaled by 1/sqrt(HD)=0.125 (exact on tf32 values)
    #pragma unroll
    for (int i = 0; i < 8; ++i) {
        int r = fr + i * 8;
        float4 v = *(const float4*)&gq[base + (size_t)(q0 + r) * HID + fc];
        v.x *= 0.125f; v.y *= 0.125f; v.z *= 0.125f; v.w *= 0.125f;
        *(float4*)&Qs[r * 68 + fc] = v;
    }
    for (int idx = tid; idx < 64 * 5; idx += 128) nearw[idx] = 0.f;

    // issue cp.async for K/V tile 0 (overlaps prel + Q-frag caching)
    {
        #pragma unroll
        for (int i = 0; i < 8; ++i) {
            int r = fr + i * 8;
            cp_async16((uint32_t)__cvta_generic_to_shared(&Ks0[r * 72 + fc]),
                       &gk[base + (size_t)(r) * HID + fc]);
            cp_async16((uint32_t)__cvta_generic_to_shared(&Vs0[r * 72 + fc]),
                       &gv[base + (size_t)(r) * HID + fc]);
        }
        cp_commit();
    }
    __syncthreads();

    // prel[r][j] = Qscaled[r] . rel_k[j]  (= 0.125 * Q.rel_k exactly)
    for (int idx = tid; idx < 64 * 6; idx += 128) {
        int r = idx / 6, j = idx % 6;
        float s = 0.f;
        #pragma unroll
        for (int d = 0; d < HD; ++d) s = fmaf(Qs[r * 68 + d], relk[j * HD + d], s);
        prel[r * 6 + j] = s;
    }

    // Cache Q A-fragments in registers (frees Qs smem for P)
    uint32_t qa[8][4];
    #pragma unroll
    for (int k8 = 0; k8 < 8; ++k8) {
        const int kc = k8 * 8;
        qa[k8][0] = fu(Qs[(rw + g    ) * 68 + kc + tig    ]);
        qa[k8][1] = fu(Qs[(rw + g + 8) * 68 + kc + tig    ]);
        qa[k8][2] = fu(Qs[(rw + g    ) * 68 + kc + tig + 4]);
        qa[k8][3] = fu(Qs[(rw + g + 8) * 68 + kc + tig + 4]);
    }

    float m0r = -1e30f, m1r = -1e30f, l0r = 0.f, l1r = 0.f;
    float o[8][4] = {};

    for (int kt = 0; kt <= qt; ++kt) {
        const int buf = kt & 1;
        float* Ks = Ks0 + buf * (64 * 72);
        float* Vs = Vs0 + buf * (64 * 72);

        // complete the single outstanding group; one barrier covers
        // load-visibility and prior-iteration buffer reuse.
        cp_wait<0>();
        __syncthreads();

        // issue next tile into buf^1 (in flight until next iteration's top)
        if (kt < qt) {
            float* Kn = Ks0 + (buf ^ 1) * (64 * 72);
            float* Vn = Vs0 + (buf ^ 1) * (64 * 72);
            const int kn = (kt + 1) * 64;
            #pragma unroll
            for (int i = 0; i < 8; ++i) {
                int r = fr + i * 8;
                cp_async16((uint32_t)__cvta_generic_to_shared(&Kn[r * 72 + fc]),
                           &gk[base + (size_t)(kn + r) * HID + fc]);
                cp_async16((uint32_t)__cvta_generic_to_shared(&Vn[r * 72 + fc]),
                           &gv[base + (size_t)(kn + r) * HID + fc]);
            }
            cp_commit();
        }

        // S = Qscaled @ K^T  (warp: 16 x 64)
        // K permuted: positions (kc+2*tig, kc+2*tig+1) hold k = (kc+tig, kc+tig+4)
        float s[8][4] = {};
        #pragma unroll
        for (int k8 = 0; k8 < 8; ++k8) {
            const int kc = k8 * 8;
            #pragma unroll
            for (int nt = 0; nt < 8; ++nt) {
                float2 kk = *(const float2*)&Ks[(nt * 8 + g) * 72 + kc + 2 * tig];
                mma_tf32(s[nt], qa[k8][0], qa[k8][1], qa[k8][2], qa[k8][3],
                         fu(kk.x), fu(kk.y));
            }
        }

        const int dq = (qt - kt) * 64;
        const bool neardiag = (dq <= 64);
        const int rl0 = rw + g, rl1 = rw + g + 8;

        // bias + mask
        float rm0 = -1e30f, rm1 = -1e30f;
        #pragma unroll
        for (int nt = 0; nt < 8; ++nt) {
            #pragma unroll
            for (int e = 0; e < 4; ++e) {
                const int rl = (e < 2) ? rl0 : rl1;
                const int col = nt * 8 + 2 * tig + (e & 1);
                const int d = dq + rl - col;
                if (d < 0) s[nt][e] = -1e30f;
                else {
                    const int id = (d >= 5) ? 0 : (5 - d);
                    s[nt][e] = s[nt][e] + prel[rl * 6 + id];
                }
            }
            rm0 = fmaxf(rm0, fmaxf(s[nt][0], s[nt][1]));
            rm1 = fmaxf(rm1, fmaxf(s[nt][2], s[nt][3]));
        }
        rm0 = fmaxf(rm0, __shfl_xor_sync(0xffffffffu, rm0, 1));
        rm0 = fmaxf(rm0, __shfl_xor_sync(0xffffffffu, rm0, 2));
        rm1 = fmaxf(rm1, __shfl_xor_sync(0xffffffffu, rm1, 1));
        rm1 = fmaxf(rm1, __shfl_xor_sync(0xffffffffu, rm1, 2));

        const float mn0 = fmaxf(m0r, rm0), mn1 = fmaxf(m1r, rm1);
        const float sc0 = __expf(m0r - mn0), sc1 = __expf(m1r - mn1);
        float ls0 = 0.f, ls1 = 0.f;
        #pragma unroll
        for (int nt = 0; nt < 8; ++nt) {
            s[nt][0] = __expf(s[nt][0] - mn0);
            s[nt][1] = __expf(s[nt][1] - mn0);
            s[nt][2] = __expf(s[nt][2] - mn1);
            s[nt][3] = __expf(s[nt][3] - mn1);
            ls0 += s[nt][0] + s[nt][1];
            ls1 += s[nt][2] + s[nt][3];
        }
        ls0 += __shfl_xor_sync(0xffffffffu, ls0, 1);
        ls0 += __shfl_xor_sync(0xffffffffu, ls0, 2);
        ls1 += __shfl_xor_sync(0xffffffffu, ls1, 1);
        ls1 += __shfl_xor_sync(0xffffffffu, ls1, 2);

        m0r = mn0; m1r = mn1;
        l0r = l0r * sc0 + ls0;
        l1r = l1r * sc1 + ls1;
        #pragma unroll
        for (int dt = 0; dt < 8; ++dt) {
            o[dt][0] *= sc0; o[dt][1] *= sc0;
            o[dt][2] *= sc1; o[dt][3] *= sc1;
        }

        if (neardiag) {
            if (tig == 0) {
                #pragma unroll
                for (int dd = 0; dd < 5; ++dd) {
                    nearw[rl0 * 5 + dd] *= sc0;
                    nearw[rl1 * 5 + dd] *= sc1;
                }
            }
            __syncwarp();
            #pragma unroll
            for (int nt = 0; nt < 8; ++nt) {
                #pragma unroll
                for (int e = 0; e < 4; ++e) {
                    const int rl = (e < 2) ? rl0 : rl1;
                    const int col = nt * 8 + 2 * tig + (e & 1);
                    const int d = dq + rl - col;
                    if (d >= 0 && d < 5) nearw[rl * 5 + d] = s[nt][e];
                }
            }
        }

        // write P into Qs (reused region), tf32-rounded patterns
        #pragma unroll
        for (int nt = 0; nt < 8; ++nt) {
            uint2 p01, p23;
            p01.x = cvt_tf32(s[nt][0]); p01.y = cvt_tf32(s[nt][1]);
            p23.x = cvt_tf32(s[nt][2]); p23.y = cvt_tf32(s[nt][3]);
            *(uint2*)&Qs[rl0 * 68 + nt * 8 + 2 * tig] = p01;
            *(uint2*)&Qs[rl1 * 68 + nt * 8 + 2 * tig] = p23;
        }
        __syncwarp();

        // O += P @ V  (B-frag reads row-major V directly: b0=V[kc+tig][dt*8+g])
        #pragma unroll
        for (int k8 = 0; k8 < 8; ++k8) {
            const int kc = k8 * 8;
            uint32_t pa0 = fu(Qs[rl0 * 68 + kc + tig    ]);
            uint32_t pa1 = fu(Qs[rl1 * 68 + kc + tig    ]);
            uint32_t pa2 = fu(Qs[rl0 * 68 + kc + tig + 4]);
            uint32_t pa3 = fu(Qs[rl1 * 68 + kc + tig + 4]);
            #pragma unroll
            for (int dt = 0; dt < 8; ++dt) {
                uint32_t b0 = fu(Vs[(kc + tig    ) * 72 + dt * 8 + g]);
                uint32_t b1 = fu(Vs[(kc + tig + 4) * 72 + dt * 8 + g]);
                mma_tf32(o[dt], pa0, pa1, pa2, pa3, b0, b1);
            }
        }
        // no trailing barrier: next iteration's top barrier guards reuse
    }
    __syncwarp();   // order tig==0 nearw writes before cross-lane epilogue reads

    // Epilogue: rel_v near/far trick + normalize
    const int rl0 = rw + g, rl1 = rw + g + 8;
    const float inv0 = 1.f / l0r, inv1 = 1.f / l1r;
    const float a0 = nearw[rl0*5+0], a1 = nearw[rl0*5+1], a2 = nearw[rl0*5+2],
                a3 = nearw[rl0*5+3], a4 = nearw[rl0*5+4];
    const float b0 = nearw[rl1*5+0], b1 = nearw[rl1*5+1], b2 = nearw[rl1*5+2],
                b3 = nearw[rl1*5+3], b4 = nearw[rl1*5+4];
    const float far0 = l0r - (a0 + a1 + a2 + a3 + a4);
    const float far1 = l1r - (b0 + b1 + b2 + b3 + b4);

    #pragma unroll
    for (int dt = 0; dt < 8; ++dt) {
        const int c = dt * 8 + 2 * tig;
        #pragma unroll
        for (int j = 0; j < 2; ++j) {
            const int cc = c + j;
            const float r5 = relv[5*HD+cc], r4 = relv[4*HD+cc], r3 = relv[3*HD+cc],
                        r2 = relv[2*HD+cc], r1 = relv[1*HD+cc], r0 = relv[cc];
            float e0 = a0*r5 + a1*r4 + a2*r3 + a3*r2 + a4*r1 + far0*r0;
            float e1 = b0*r5 + b1*r4 + b2*r3 + b3*r2 + b4*r1 + far1*r0;
            gctx[base + (size_t)(q0 + rl0) * HID + cc] = (o[dt][j]     + e0) * inv0;
            gctx[base + (size_t)(q0 + rl1) * HID + cc] = (o[dt][2 + j] + e1) * inv1;
        }
    }
}

extern "C" void kernel_launch(void* const* d_in, const int* in_sizes, int n_in,
                              void* d_out, int out_size) {
    (void)in_sizes; (void)n_in; (void)out_size;
    const float* query = (const float*)d_in[0];
    const float* key   = (const float*)d_in[1];
    const float* value = (const float*)d_in[2];
    const float* Wq = (const float*)d_in[3];
    const float* bq = (const float*)d_in[4];
    const float* Wk = (const float*)d_in[5];
    const float* bk = (const float*)d_in[6];
    const float* Wv = (const float*)d_in[7];
    const float* bv = (const float*)d_in[8];
    const float* Wo = (const float*)d_in[9];
    const float* bo = (const float*)d_in[10];
    const float* relk = (const float*)d_in[11];
    const float* relv = (const float*)d_in[12];

    float *pq, *pk, *pv, *pctx;
    cudaGetSymbolAddress((void**)&pq,  g_q);
    cudaGetSymbolAddress((void**)&pk,  g_k);
    cudaGetSymbolAddress((void**)&pv,  g_v);
    cudaGetSymbolAddress((void**)&pctx, g_ctx);

    const int GSMEM = 2 * (AS_STRIDE + BS_STRIDE) * (int)sizeof(uint32_t); // 55296
    cudaFuncSetAttribute(gemm_nt_tc,
                         cudaFuncAttributeMaxDynamicSharedMemorySize, GSMEM);

    // 1) QKV projections (one launch, grid.z = 3) — tf32-pre-rounded;
    //    K additionally column-permuted for vectorized attention loads
    GArgs qkv;
    qkv.A[0] = query; qkv.W[0] = Wq; qkv.bias[0] = bq; qkv.C[0] = pq; qkv.round_out[0] = 1; qkv.perm_out[0] = 0;
    qkv.A[1] = key;   qkv.W[1] = Wk; qkv.bias[1] = bk; qkv.C[1] = pk; qkv.round_out[1] = 1; qkv.perm_out[1] = 1;
    qkv.A[2] = value; qkv.W[2] = Wv; qkv.bias[2] = bv; qkv.C[2] = pv; qkv.round_out[2] = 1; qkv.perm_out[2] = 0;
    gemm_nt_tc<<<dim3(HID/64, (BB*LL)/128, 3), 256, GSMEM>>>(qkv);

    // 2) attention — 64 q-rows per CTA, 128 threads
    const int SMEM = (64*68 + 4*64*72 + 64*6 + 64*5) * (int)sizeof(float);  // 93952
    cudaFuncSetAttribute(attn_tc,
                         cudaFuncAttributeMaxDynamicSharedMemorySize, SMEM);
    attn_tc<<<dim3(LL/64, HEADS, BB), 128, SMEM>>>(pq, pk, pv, relk, relv, pctx);

    // 3) output projection — exact fp32 output
    GArgs og;
    og.A[0] = pctx; og.W[0] = Wo; og.bias[0] = bo; og.C[0] = (float*)d_out; og.round_out[0] = 0; og.perm_out[0] = 0;
    og.A[1] = og.A[0]; og.W[1] = og.W[0]; og.bias[1] = og.bias[0]; og.C[1] = og.C[0]; og.round_out[1] = 0; og.perm_out[1] = 0;
    og.A[2] = og.A[0]; og.W[2] = og.W[0]; og.bias[2] = og.bias[0]; og.C[2] = og.C[0]; og.round_out[2] = 0; og.perm_out[2] = 0;
    gemm_nt_tc<<<dim3(HID/64, (BB*LL)/128, 1), 256, GSMEM>>>(og);
}

// round 15
// speedup vs baseline: 1.0931x; 1.0215x over previous
#include <cuda_runtime.h>
#include <math.h>
#include <stdint.h>

#define BB 4
#define LL 1024
#define HID 512
#define HEADS 8
#define HD 64

// Scratch (device globals: allocation-free)
__device__ float g_q[BB*LL*HID];
__device__ float g_k[BB*LL*HID];
__device__ float g_v[BB*LL*HID];   // V stored TRANSPOSED: [b][h][d][token'] (token perm8)
__device__ float g_ctx[BB*LL*HID];

struct GArgs {
    const float* A[3];
    const float* W[3];
    const float* bias[3];
    float* C[3];
    int round_out[3];   // 1: store tf32-rounded C (q/k/v scratch)
    int perm_out[3];    // 1: permute columns within 8-groups (K scratch)
    int trans_out[3];   // 1: store transposed d-major with permuted tokens (V scratch)
};

// tf32 round (rna) -> 32-bit pattern in a b32 register
__device__ __forceinline__ uint32_t cvt_tf32(float x) {
    uint32_t r;
    asm("cvt.rna.tf32.f32 %0, %1;" : "=r"(r) : "f"(x));
    return r;
}
__device__ __forceinline__ uint32_t fu(float x) { return __float_as_uint(x); }
__device__ __forceinline__ uint4 cvt4(float4 v) {
    uint4 u;
    u.x = cvt_tf32(v.x); u.y = cvt_tf32(v.y);
    u.z = cvt_tf32(v.z); u.w = cvt_tf32(v.w);
    return u;
}

// permutation within each 8-group: x -> 2*(x&3) + ((x>>2)&1), group base kept
__device__ __forceinline__ int perm8(int c) {
    return (c & ~7) | ((2 * (c & 3)) | ((c >> 2) & 1));
}

__device__ __forceinline__ void cp_async16(uint32_t smem_dst, const void* gmem_src) {
    asm volatile("cp.async.cg.shared.global [%0], [%1], 16;\n"
                 :: "r"(smem_dst), "l"(gmem_src));
}
__device__ __forceinline__ void cp_commit() {
    asm volatile("cp.async.commit_group;\n");
}
template <int N>
__device__ __forceinline__ void cp_wait() {
    asm volatile("cp.async.wait_group %0;\n" :: "n"(N));
}

__device__ __forceinline__ void mma_tf32(float c[4],
    uint32_t a0, uint32_t a1, uint32_t a2, uint32_t a3,
    uint32_t b0, uint32_t b1)
{
    asm volatile(
        "mma.sync.aligned.m16n8k8.row.col.f32.tf32.tf32.f32 "
        "{%0,%1,%2,%3}, {%4,%5,%6,%7}, {%8,%9}, {%0,%1,%2,%3};\n"
        : "+f"(c[0]), "+f"(c[1]), "+f"(c[2]), "+f"(c[3])
        : "r"(a0), "r"(a1), "r"(a2), "r"(a3), "r"(b0), "r"(b1));
}

// ---------------------------------------------------------------------------
// C[m,n] = sum_k A[m,k]*W[n,k] + bias[n]   (NT, both K-contiguous row-major)
// CTA tile 128(M) x 64(N), 256 threads = 8 warps (4m x 2n), warp 32x32.
// Register-staged double-buffered smem pipeline; 1 barrier per k-tile.
// ---------------------------------------------------------------------------
#define AS_STRIDE 4608   // 128*36
#define BS_STRIDE 2304   // 64*36
__global__ __launch_bounds__(256) void gemm_nt_tc(GArgs args) {
    const int N = HID, K = HID;
    extern __shared__ uint32_t smg[];
    uint32_t* As = smg;                    // [2][128*36]
    uint32_t* Bs = smg + 2 * AS_STRIDE;    // [2][64*36]

    const int z = blockIdx.z;
    const float* __restrict__ A = args.A[z];
    const float* __restrict__ W = args.W[z];
    const float* __restrict__ bias = args.bias[z];
    float* __restrict__ C = args.C[z];
    const bool rnd = args.round_out[z] != 0;
    const bool prm = args.perm_out[z] != 0;
    const bool trv = args.trans_out[z] != 0;

    const int tid = threadIdx.x;
    const int wid = tid >> 5, lane = tid & 31;
    const int g = lane >> 2, tig = lane & 3;
    const int wm = wid >> 1, wn = wid & 1;
    const int m0 = blockIdx.y * 128, n0 = blockIdx.x * 64;

    const int fa_r = tid >> 3, fa_c = (tid & 7) * 4;  // A/B load coords

    float c[2][4][4] = {};
    float4 ra[4], rb[2];

    // prologue: tile 0 -> regs -> smem[0]
    #pragma unroll
    for (int i = 0; i < 4; ++i)
        ra[i] = *(const float4*)&A[(size_t)(m0 + fa_r + i * 32) * K + fa_c];
    #pragma unroll
    for (int i = 0; i < 2; ++i)
        rb[i] = *(const float4*)&W[(size_t)(n0 + fa_r + i * 32) * K + fa_c];
    #pragma unroll
    for (int i = 0; i < 4; ++i)
        *(uint4*)&As[(fa_r + i * 32) * 36 + fa_c] = cvt4(ra[i]);
    #pragma unroll
    for (int i = 0; i < 2; ++i)
        *(uint4*)&Bs[(fa_r + i * 32) * 36 + fa_c] = cvt4(rb[i]);
    __syncthreads();

    #pragma unroll 2
    for (int k0 = 0; k0 < K; k0 += 32) {
        const int buf = (k0 >> 5) & 1;
        const uint32_t* Ac = As + buf * AS_STRIDE;
        const uint32_t* Bc = Bs + buf * BS_STRIDE;
        const bool has_next = (k0 + 32) < K;

        if (has_next) {
            const int k1 = k0 + 32;
            #pragma unroll
            for (int i = 0; i < 4; ++i)
                ra[i] = *(const float4*)&A[(size_t)(m0 + fa_r + i * 32) * K + k1 + fa_c];
            #pragma unroll
            for (int i = 0; i < 2; ++i)
                rb[i] = *(const float4*)&W[(size_t)(n0 + fa_r + i * 32) * K + k1 + fa_c];
        }

        #pragma unroll
        for (int ks = 0; ks < 4; ++ks) {
            const int kc = ks * 8;
            uint32_t a[2][4];
            #pragma unroll
            for (int mt = 0; mt < 2; ++mt) {
                const int row = wm * 32 + mt * 16;
                a[mt][0] = Ac[(row + g    ) * 36 + kc + tig    ];
                a[mt][1] = Ac[(row + g + 8) * 36 + kc + tig    ];
                a[mt][2] = Ac[(row + g    ) * 36 + kc + tig + 4];
                a[mt][3] = Ac[(row + g + 8) * 36 + kc + tig + 4];
            }
            uint32_t b[4][2];
            #pragma unroll
            for (int nt = 0; nt < 4; ++nt) {
                const int col = wn * 32 + nt * 8;
                b[nt][0] = Bc[(col + g) * 36 + kc + tig    ];
                b[nt][1] = Bc[(col + g) * 36 + kc + tig + 4];
            }
            #pragma unroll
            for (int mt = 0; mt < 2; ++mt)
                #pragma unroll
                for (int nt = 0; nt < 4; ++nt)
                    mma_tf32(c[mt][nt], a[mt][0], a[mt][1], a[mt][2], a[mt][3],
                             b[nt][0], b[nt][1]);
        }

        if (has_next) {
            uint32_t* An = As + (buf ^ 1) * AS_STRIDE;
            uint32_t* Bn = Bs + (buf ^ 1) * BS_STRIDE;
            #pragma unroll
            for (int i = 0; i < 4; ++i)
                *(uint4*)&An[(fa_r + i * 32) * 36 + fa_c] = cvt4(ra[i]);
            #pragma unroll
            for (int i = 0; i < 2; ++i)
                *(uint4*)&Bn[(fa_r + i * 32) * 36 + fa_c] = cvt4(rb[i]);
        }
        __syncthreads();
    }

    #pragma unroll
    for (int mt = 0; mt < 2; ++mt) {
        const int row = m0 + wm * 32 + mt * 16 + g;
        #pragma unroll
        for (int nt = 0; nt < 4; ++nt) {
            const int col = n0 + wn * 32 + nt * 8 + 2 * tig;
            const float bx = bias[col], by = bias[col + 1];
            float v0 = c[mt][nt][0] + bx, v1 = c[mt][nt][1] + by;
            float v2 = c[mt][nt][2] + bx, v3 = c[mt][nt][3] + by;
            if (rnd) {
                v0 = __uint_as_float(cvt_tf32(v0));
                v1 = __uint_as_float(cvt_tf32(v1));
                v2 = __uint_as_float(cvt_tf32(v2));
                v3 = __uint_as_float(cvt_tf32(v3));
            }
            if (trv) {
                // V scratch: transposed [b][h][d][token'], token perm8-permuted.
                // col is even, so col+1 shares the same head (col&63 <= 62).
                const int hh = col >> 6, dd = col & 63;
                const int bi = row / LL;
                const int t0 = perm8(row % LL);
                const int t1 = perm8((row + 8) % LL);
                float* vbase = &C[(((size_t)bi * HEADS + hh) * HD + dd) * LL];
                vbase[t0]      = v0;
                vbase[LL + t0] = v1;   // d+1, same token
                vbase[t1]      = v2;
                vbase[LL + t1] = v3;
            } else if (prm) {   // K scratch: permuted columns (scalar stores)
                const int p0c = perm8(col);
                const int p1c = perm8(col + 1);
                C[(size_t)row * N + p0c] = v0;
                C[(size_t)row * N + p1c] = v1;
                C[(size_t)(row + 8) * N + p0c] = v2;
                C[(size_t)(row + 8) * N + p1c] = v3;
            } else {
                *(float2*)&C[(size_t)row * N + col] = make_float2(v0, v1);
                *(float2*)&C[(size_t)(row + 8) * N + col] = make_float2(v2, v3);
            }
        }
    }
}

// ---------------------------------------------------------------------------
// Flash-style causal attention with relative-position terms, tf32 mma.
// CTA: 64 q-rows per (b,h); 128 threads = 4 warps; warp owns 16 q-rows.
// Q/K/V arrive pre-rounded to tf32 (GEMM epilogue), no cvt on load.
// K: column-permuted (perm8)  -> S-loop B-frags are single LDS.64.
// V: d-major transposed, token-permuted -> PV B-frags are single LDS.64.
// K/V cp.async double-buffered; one __syncthreads per kt-iteration.
// ---------------------------------------------------------------------------
__global__ __launch_bounds__(128) void attn_tc(
    const float* __restrict__ gq, const float* __restrict__ gk,
    const float* __restrict__ gvt, const float* __restrict__ relk,
    const float* __restrict__ relv, float* __restrict__ gctx)
{
    extern __shared__ float sm[];
    float* Qs   = sm;                  // 64*68, reused as Ps after Q frags cached
    float* Ks0  = Qs + 64 * 68;        // [2][64*72]  (permuted k-columns)
    float* Vs0  = Ks0 + 2 * 64 * 72;   // [2][64*72]  rows = d, cols = permuted keys
    float* prel = Vs0 + 2 * 64 * 72;   // [64][6]  (pre-scaled by 0.125 via Q)
    float* nearw = prel + 64 * 6;      // [64][5]

    const int tid = threadIdx.x;
    const int wid = tid >> 5, lane = tid & 31;
    const int g = lane >> 2, tig = lane & 3;
    const int qt = blockIdx.x;
    const int h = blockIdx.y, b = blockIdx.z;
    const int q0 = qt * 64;
    const int rw = wid * 16;           // warp's first q-row (local)
    const size_t base  = ((size_t)b * LL) * HID + (size_t)h * HD;
    const size_t vbase = ((size_t)(b * HEADS + h) * HD) * LL;   // transposed V

    const int fr = tid >> 4, fc = (tid & 15) * 4;   // tile load coords

    // Load Q tile, pre-scaled by 1/sqrt(HD)=0.125 (exact on tf32 values)
    #pragma unroll
    for (int i = 0; i < 8; ++i) {
        int r = fr + i * 8;
        float4 v = *(const float4*)&gq[base + (size_t)(q0 + r) * HID + fc];
        v.x *= 0.125f; v.y *= 0.125f; v.z *= 0.125f; v.w *= 0.125f;
        *(float4*)&Qs[r * 68 + fc] = v;
    }
    for (int idx = tid; idx < 64 * 5; idx += 128) nearw[idx] = 0.f;

    // issue cp.async for K/V tile 0 (overlaps prel + Q-frag caching)
    {
        #pragma unroll
        for (int i = 0; i < 8; ++i) {
            int r = fr + i * 8;
            cp_async16((uint32_t)__cvta_generic_to_shared(&Ks0[r * 72 + fc]),
                       &gk[base + (size_t)(r) * HID + fc]);
            cp_async16((uint32_t)__cvta_generic_to_shared(&Vs0[r * 72 + fc]),
                       &gvt[vbase + (size_t)r * LL + fc]);
        }
        cp_commit();
    }
    __syncthreads();

    // prel[r][j] = Qscaled[r] . rel_k[j]  (= 0.125 * Q.rel_k exactly)
    for (int idx = tid; idx < 64 * 6; idx += 128) {
        int r = idx / 6, j = idx % 6;
        float s = 0.f;
        #pragma unroll
        for (int d = 0; d < HD; ++d) s = fmaf(Qs[r * 68 + d], relk[j * HD + d], s);
        prel[r * 6 + j] = s;
    }

    // Cache Q A-fragments in registers (frees Qs smem for P)
    uint32_t qa[8][4];
    #pragma unroll
    for (int k8 = 0; k8 < 8; ++k8) {
        const int kc = k8 * 8;
        qa[k8][0] = fu(Qs[(rw + g    ) * 68 + kc + tig    ]);
        qa[k8][1] = fu(Qs[(rw + g + 8) * 68 + kc + tig    ]);
        qa[k8][2] = fu(Qs[(rw + g    ) * 68 + kc + tig + 4]);
        qa[k8][3] = fu(Qs[(rw + g + 8) * 68 + kc + tig + 4]);
    }

    float m0r = -1e30f, m1r = -1e30f, l0r = 0.f, l1r = 0.f;
    float o[8][4] = {};

    for (int kt = 0; kt <= qt; ++kt) {
        const int buf = kt & 1;
        float* Ks = Ks0 + buf * (64 * 72);
        float* Vs = Vs0 + buf * (64 * 72);

        // complete the single outstanding group; one barrier covers
        // load-visibility and prior-iteration buffer reuse.
        cp_wait<0>();
        __syncthreads();

        // issue next tile into buf^1 (in flight until next iteration's top)
        if (kt < qt) {
            float* Kn = Ks0 + (buf ^ 1) * (64 * 72);
            float* Vn = Vs0 + (buf ^ 1) * (64 * 72);
            const int kn = (kt + 1) * 64;
            #pragma unroll
            for (int i = 0; i < 8; ++i) {
                int r = fr + i * 8;
                cp_async16((uint32_t)__cvta_generic_to_shared(&Kn[r * 72 + fc]),
                           &gk[base + (size_t)(kn + r) * HID + fc]);
                cp_async16((uint32_t)__cvta_generic_to_shared(&Vn[r * 72 + fc]),
                           &gvt[vbase + (size_t)r * LL + kn + fc]);
            }
            cp_commit();
        }

        // S = Qscaled @ K^T  (warp: 16 x 64)
        // K permuted: positions (kc+2tig, kc+2tig+1) hold k = (kc+tig, kc+tig+4)
        float s[8][4] = {};
        #pragma unroll
        for (int k8 = 0; k8 < 8; ++k8) {
            const int kc = k8 * 8;
            #pragma unroll
            for (int nt = 0; nt < 8; ++nt) {
                float2 kk = *(const float2*)&Ks[(nt * 8 + g) * 72 + kc + 2 * tig];
                mma_tf32(s[nt], qa[k8][0], qa[k8][1], qa[k8][2], qa[k8][3],
                         fu(kk.x), fu(kk.y));
            }
        }

        const int dq = (qt - kt) * 64;
        const bool neardiag = (dq <= 64);
        const int rl0 = rw + g, rl1 = rw + g + 8;

        // bias + mask
        float rm0 = -1e30f, rm1 = -1e30f;
        #pragma unroll
        for (int nt = 0; nt < 8; ++nt) {
            #pragma unroll
            for (int e = 0; e < 4; ++e) {
                const int rl = (e < 2) ? rl0 : rl1;
                const int col = nt * 8 + 2 * tig + (e & 1);
                const int d = dq + rl - col;
                if (d < 0) s[nt][e] = -1e30f;
                else {
                    const int id = (d >= 5) ? 0 : (5 - d);
                    s[nt][e] = s[nt][e] + prel[rl * 6 + id];
                }
            }
            rm0 = fmaxf(rm0, fmaxf(s[nt][0], s[nt][1]));
            rm1 = fmaxf(rm1, fmaxf(s[nt][2], s[nt][3]));
        }
        rm0 = fmaxf(rm0, __shfl_xor_sync(0xffffffffu, rm0, 1));
        rm0 = fmaxf(rm0, __shfl_xor_sync(0xffffffffu, rm0, 2));
        rm1 = fmaxf(rm1, __shfl_xor_sync(0xffffffffu, rm1, 1));
        rm1 = fmaxf(rm1, __shfl_xor_sync(0xffffffffu, rm1, 2));

        const float mn0 = fmaxf(m0r, rm0), mn1 = fmaxf(m1r, rm1);
        const float sc0 = __expf(m0r - mn0), sc1 = __expf(m1r - mn1);
        float ls0 = 0.f, ls1 = 0.f;
        #pragma unroll
        for (int nt = 0; nt < 8; ++nt) {
            s[nt][0] = __expf(s[nt][0] - mn0);
            s[nt][1] = __expf(s[nt][1] - mn0);
            s[nt][2] = __expf(s[nt][2] - mn1);
            s[nt][3] = __expf(s[nt][3] - mn1);
            ls0 += s[nt][0] + s[nt][1];
            ls1 += s[nt][2] + s[nt][3];
        }
        ls0 += __shfl_xor_sync(0xffffffffu, ls0, 1);
        ls0 += __shfl_xor_sync(0xffffffffu, ls0, 2);
        ls1 += __shfl_xor_sync(0xffffffffu, ls1, 1);
        ls1 += __shfl_xor_sync(0xffffffffu, ls1, 2);

        m0r = mn0; m1r = mn1;
        l0r = l0r * sc0 + ls0;
        l1r = l1r * sc1 + ls1;
        #pragma unroll
        for (int dt = 0; dt < 8; ++dt) {
            o[dt][0] *= sc0; o[dt][1] *= sc0;
            o[dt][2] *= sc1; o[dt][3] *= sc1;
        }

        if (neardiag) {
            if (tig == 0) {
                #pragma unroll
                for (int dd = 0; dd < 5; ++dd) {
                    nearw[rl0 * 5 + dd] *= sc0;
                    nearw[rl1 * 5 + dd] *= sc1;
                }
            }
            __syncwarp();
            #pragma unroll
            for (int nt = 0; nt < 8; ++nt) {
                #pragma unroll
                for (int e = 0; e < 4; ++e) {
                    const int rl = (e < 2) ? rl0 : rl1;
                    const int col = nt * 8 + 2 * tig + (e & 1);
                    const int d = dq + rl - col;
                    if (d >= 0 && d < 5) nearw[rl * 5 + d] = s[nt][e];
                }
            }
        }

        // write P into Qs (reused region), tf32-rounded patterns
        #pragma unroll
        for (int nt = 0; nt < 8; ++nt) {
            uint2 p01, p23;
            p01.x = cvt_tf32(s[nt][0]); p01.y = cvt_tf32(s[nt][1]);
            p23.x = cvt_tf32(s[nt][2]); p23.y = cvt_tf32(s[nt][3]);
            *(uint2*)&Qs[rl0 * 68 + nt * 8 + 2 * tig] = p01;
            *(uint2*)&Qs[rl1 * 68 + nt * 8 + 2 * tig] = p23;
        }
        __syncwarp();

        // O += P @ V   (V d-major + permuted keys: both B-frag elements
        //  adjacent -> single LDS.64 at Vs[(dt*8+g)*72 + kc + 2*tig])
        #pragma unroll
        for (int k8 = 0; k8 < 8; ++k8) {
            const int kc = k8 * 8;
            uint32_t pa0 = fu(Qs[rl0 * 68 + kc + tig    ]);
            uint32_t pa1 = fu(Qs[rl1 * 68 + kc + tig    ]);
            uint32_t pa2 = fu(Qs[rl0 * 68 + kc + tig + 4]);
            uint32_t pa3 = fu(Qs[rl1 * 68 + kc + tig + 4]);
            #pragma unroll
            for (int dt = 0; dt < 8; ++dt) {
                float2 vv = *(const float2*)&Vs[(dt * 8 + g) * 72 + kc + 2 * tig];
                mma_tf32(o[dt], pa0, pa1, pa2, pa3, fu(vv.x), fu(vv.y));
            }
        }
        // no trailing barrier: next iteration's top barrier guards reuse
    }
    __syncwarp();   // order tig==0 nearw writes before cross-lane epilogue reads

    // Epilogue: rel_v near/far trick + normalize
    const int rl0 = rw + g, rl1 = rw + g + 8;
    const float inv0 = 1.f / l0r, inv1 = 1.f / l1r;
    const float a0 = nearw[rl0*5+0], a1 = nearw[rl0*5+1], a2 = nearw[rl0*5+2],
                a3 = nearw[rl0*5+3], a4 = nearw[rl0*5+4];
    const float b0 = nearw[rl1*5+0], b1 = nearw[rl1*5+1], b2 = nearw[rl1*5+2],
                b3 = nearw[rl1*5+3], b4 = nearw[rl1*5+4];
    const float far0 = l0r - (a0 + a1 + a2 + a3 + a4);
    const float far1 = l1r - (b0 + b1 + b2 + b3 + b4);

    #pragma unroll
    for (int dt = 0; dt < 8; ++dt) {
        const int c = dt * 8 + 2 * tig;
        #pragma unroll
        for (int j = 0; j < 2; ++j) {
            const int cc = c + j;
            const float r5 = relv[5*HD+cc], r4 = relv[4*HD+cc], r3 = relv[3*HD+cc],
                        r2 = relv[2*HD+cc], r1 = relv[1*HD+cc], r0 = relv[cc];
            float e0 = a0*r5 + a1*r4 + a2*r3 + a3*r2 + a4*r1 + far0*r0;
            float e1 = b0*r5 + b1*r4 + b2*r3 + b3*r2 + b4*r1 + far1*r0;
            gctx[base + (size_t)(q0 + rl0) * HID + cc] = (o[dt][j]     + e0) * inv0;
            gctx[base + (size_t)(q0 + rl1) * HID + cc] = (o[dt][2 + j] + e1) * inv1;
        }
    }
}

extern "C" void kernel_launch(void* const* d_in, const int* in_sizes, int n_in,
                              void* d_out, int out_size) {
    (void)in_sizes; (void)n_in; (void)out_size;
    const float* query = (const float*)d_in[0];
    const float* key   = (const float*)d_in[1];
    const float* value = (const float*)d_in[2];
    const float* Wq = (const float*)d_in[3];
    const float* bq = (const float*)d_in[4];
    const float* Wk = (const float*)d_in[5];
    const float* bk = (const float*)d_in[6];
    const float* Wv = (const float*)d_in[7];
    const float* bv = (const float*)d_in[8];
    const float* Wo = (const float*)d_in[9];
    const float* bo = (const float*)d_in[10];
    const float* relk = (const float*)d_in[11];
    const float* relv = (const float*)d_in[12];

    float *pq, *pk, *pv, *pctx;
    cudaGetSymbolAddress((void**)&pq,  g_q);
    cudaGetSymbolAddress((void**)&pk,  g_k);
    cudaGetSymbolAddress((void**)&pv,  g_v);
    cudaGetSymbolAddress((void**)&pctx, g_ctx);

    const int GSMEM = 2 * (AS_STRIDE + BS_STRIDE) * (int)sizeof(uint32_t); // 55296
    cudaFuncSetAttribute(gemm_nt_tc,
                         cudaFuncAttributeMaxDynamicSharedMemorySize, GSMEM);

    // 1) QKV projections — tf32-pre-rounded; K column-permuted; V transposed
    GArgs qkv;
    qkv.A[0] = query; qkv.W[0] = Wq; qkv.bias[0] = bq; qkv.C[0] = pq;
    qkv.round_out[0] = 1; qkv.perm_out[0] = 0; qkv.trans_out[0] = 0;
    qkv.A[1] = key;   qkv.W[1] = Wk; qkv.bias[1] = bk; qkv.C[1] = pk;
    qkv.round_out[1] = 1; qkv.perm_out[1] = 1; qkv.trans_out[1] = 0;
    qkv.A[2] = value; qkv.W[2] = Wv; qkv.bias[2] = bv; qkv.C[2] = pv;
    qkv.round_out[2] = 1; qkv.perm_out[2] = 0; qkv.trans_out[2] = 1;
    gemm_nt_tc<<<dim3(HID/64, (BB*LL)/128, 3), 256, GSMEM>>>(qkv);

    // 2) attention — 64 q-rows per CTA, 128 threads
    const int SMEM = (64*68 + 4*64*72 + 64*6 + 64*5) * (int)sizeof(float);  // 93952
    cudaFuncSetAttribute(attn_tc,
                         cudaFuncAttributeMaxDynamicSharedMemorySize, SMEM);
    attn_tc<<<dim3(LL/64, HEADS, BB), 128, SMEM>>>(pq, pk, pv, relk, relv, pctx);

    // 3) output projection — exact fp32 output
    GArgs og;
    og.A[0] = pctx; og.W[0] = Wo; og.bias[0] = bo; og.C[0] = (float*)d_out;
    og.round_out[0] = 0; og.perm_out[0] = 0; og.trans_out[0] = 0;
    og.A[1] = og.A[0]; og.W[1] = og.W[0]; og.bias[1] = og.bias[0]; og.C[1] = og.C[0];
    og.round_out[1] = 0; og.perm_out[1] = 0; og.trans_out[1] = 0;
    og.A[2] = og.A[0]; og.W[2] = og.W[0]; og.bias[2] = og.bias[0]; og.C[2] = og.C[0];
    og.round_out[2] = 0; og.perm_out[2] = 0; og.trans_out[2] = 0;
    gemm_nt_tc<<<dim3(HID/64, (BB*LL)/128, 1), 256, GSMEM>>>(og);
}

// round 16
// speedup vs baseline: 1.1025x; 1.0086x over previous
#include <cuda_runtime.h>
#include <math.h>
#include <stdint.h>

#define BB 4
#define LL 1024
#define HID 512
#define HEADS 8
#define HD 64

// Scratch (device globals: allocation-free)
__device__ float g_q[BB*LL*HID];
__device__ float g_k[BB*LL*HID];   // K stored with perm16 columns within 16-groups
__device__ float g_v[BB*LL*HID];   // V TRANSPOSED [b][h][d][token'], token perm16
__device__ float g_ctx[BB*LL*HID];

struct GArgs {
    const float* A[3];
    const float* W[3];
    const float* bias[3];
    float* C[3];
    int round_out[3];   // 1: store tf32-rounded C (q/k/v scratch)
    int perm_out[3];    // 1: perm16 columns (K scratch)
    int trans_out[3];   // 1: transposed d-major, perm16 tokens (V scratch)
};

// tf32 round (rna) -> 32-bit pattern in a b32 register
__device__ __forceinline__ uint32_t cvt_tf32(float x) {
    uint32_t r;
    asm("cvt.rna.tf32.f32 %0, %1;" : "=r"(r) : "f"(x));
    return r;
}
__device__ __forceinline__ uint32_t fu(float x) { return __float_as_uint(x); }
__device__ __forceinline__ uint4 cvt4(float4 v) {
    uint4 u;
    u.x = cvt_tf32(v.x); u.y = cvt_tf32(v.y);
    u.z = cvt_tf32(v.z); u.w = cvt_tf32(v.w);
    return u;
}

// permutation within each 16-group: l -> 4*(l&3) + ((l>>2)&3)
// (position 4*tig+b holds logical offset tig + 4b; one float4 = both
//  k8-chunk fragments {tig,tig+4} and {tig+8,tig+12})
__device__ __forceinline__ int perm16(int c) {
    return (c & ~15) | ((4 * (c & 3)) | ((c >> 2) & 3));
}

__device__ __forceinline__ void cp_async16(uint32_t smem_dst, const void* gmem_src) {
    asm volatile("cp.async.cg.shared.global [%0], [%1], 16;\n"
                 :: "r"(smem_dst), "l"(gmem_src));
}
__device__ __forceinline__ void cp_commit() {
    asm volatile("cp.async.commit_group;\n");
}
template <int N>
__device__ __forceinline__ void cp_wait() {
    asm volatile("cp.async.wait_group %0;\n" :: "n"(N));
}

__device__ __forceinline__ void mma_tf32(float c[4],
    uint32_t a0, uint32_t a1, uint32_t a2, uint32_t a3,
    uint32_t b0, uint32_t b1)
{
    asm volatile(
        "mma.sync.aligned.m16n8k8.row.col.f32.tf32.tf32.f32 "
        "{%0,%1,%2,%3}, {%4,%5,%6,%7}, {%8,%9}, {%0,%1,%2,%3};\n"
        : "+f"(c[0]), "+f"(c[1]), "+f"(c[2]), "+f"(c[3])
        : "r"(a0), "r"(a1), "r"(a2), "r"(a3), "r"(b0), "r"(b1));
}

// ---------------------------------------------------------------------------
// C[m,n] = sum_k A[m,k]*W[n,k] + bias[n]   (NT, both K-contiguous row-major)
// CTA tile 128(M) x 64(N), 256 threads = 8 warps (4m x 2n), warp 32x32.
// Register-staged double-buffered smem pipeline; 1 barrier per k-tile.
// ---------------------------------------------------------------------------
#define AS_STRIDE 4608   // 128*36
#define BS_STRIDE 2304   // 64*36
__global__ __launch_bounds__(256) void gemm_nt_tc(GArgs args) {
    const int N = HID, K = HID;
    extern __shared__ uint32_t smg[];
    uint32_t* As = smg;                    // [2][128*36]
    uint32_t* Bs = smg + 2 * AS_STRIDE;    // [2][64*36]

    const int z = blockIdx.z;
    const float* __restrict__ A = args.A[z];
    const float* __restrict__ W = args.W[z];
    const float* __restrict__ bias = args.bias[z];
    float* __restrict__ C = args.C[z];
    const bool rnd = args.round_out[z] != 0;
    const bool prm = args.perm_out[z] != 0;
    const bool trv = args.trans_out[z] != 0;

    const int tid = threadIdx.x;
    const int wid = tid >> 5, lane = tid & 31;
    const int g = lane >> 2, tig = lane & 3;
    const int wm = wid >> 1, wn = wid & 1;
    const int m0 = blockIdx.y * 128, n0 = blockIdx.x * 64;

    const int fa_r = tid >> 3, fa_c = (tid & 7) * 4;  // A/B load coords

    float c[2][4][4] = {};
    float4 ra[4], rb[2];

    // prologue: tile 0 -> regs -> smem[0]
    #pragma unroll
    for (int i = 0; i < 4; ++i)
        ra[i] = *(const float4*)&A[(size_t)(m0 + fa_r + i * 32) * K + fa_c];
    #pragma unroll
    for (int i = 0; i < 2; ++i)
        rb[i] = *(const float4*)&W[(size_t)(n0 + fa_r + i * 32) * K + fa_c];
    #pragma unroll
    for (int i = 0; i < 4; ++i)
        *(uint4*)&As[(fa_r + i * 32) * 36 + fa_c] = cvt4(ra[i]);
    #pragma unroll
    for (int i = 0; i < 2; ++i)
        *(uint4*)&Bs[(fa_r + i * 32) * 36 + fa_c] = cvt4(rb[i]);
    __syncthreads();

    #pragma unroll 2
    for (int k0 = 0; k0 < K; k0 += 32) {
        const int buf = (k0 >> 5) & 1;
        const uint32_t* Ac = As + buf * AS_STRIDE;
        const uint32_t* Bc = Bs + buf * BS_STRIDE;
        const bool has_next = (k0 + 32) < K;

        if (has_next) {
            const int k1 = k0 + 32;
            #pragma unroll
            for (int i = 0; i < 4; ++i)
                ra[i] = *(const float4*)&A[(size_t)(m0 + fa_r + i * 32) * K + k1 + fa_c];
            #pragma unroll
            for (int i = 0; i < 2; ++i)
                rb[i] = *(const float4*)&W[(size_t)(n0 + fa_r + i * 32) * K + k1 + fa_c];
        }

        #pragma unroll
        for (int ks = 0; ks < 4; ++ks) {
            const int kc = ks * 8;
            uint32_t a[2][4];
            #pragma unroll
            for (int mt = 0; mt < 2; ++mt) {
                const int row = wm * 32 + mt * 16;
                a[mt][0] = Ac[(row + g    ) * 36 + kc + tig    ];
                a[mt][1] = Ac[(row + g + 8) * 36 + kc + tig    ];
                a[mt][2] = Ac[(row + g    ) * 36 + kc + tig + 4];
                a[mt][3] = Ac[(row + g + 8) * 36 + kc + tig + 4];
            }
            uint32_t b[4][2];
            #pragma unroll
            for (int nt = 0; nt < 4; ++nt) {
                const int col = wn * 32 + nt * 8;
                b[nt][0] = Bc[(col + g) * 36 + kc + tig    ];
                b[nt][1] = Bc[(col + g) * 36 + kc + tig + 4];
            }
            #pragma unroll
            for (int mt = 0; mt < 2; ++mt)
                #pragma unroll
                for (int nt = 0; nt < 4; ++nt)
                    mma_tf32(c[mt][nt], a[mt][0], a[mt][1], a[mt][2], a[mt][3],
                             b[nt][0], b[nt][1]);
        }

        if (has_next) {
            uint32_t* An = As + (buf ^ 1) * AS_STRIDE;
            uint32_t* Bn = Bs + (buf ^ 1) * BS_STRIDE;
            #pragma unroll
            for (int i = 0; i < 4; ++i)
                *(uint4*)&An[(fa_r + i * 32) * 36 + fa_c] = cvt4(ra[i]);
            #pragma unroll
            for (int i = 0; i < 2; ++i)
                *(uint4*)&Bn[(fa_r + i * 32) * 36 + fa_c] = cvt4(rb[i]);
        }
        __syncthreads();
    }

    #pragma unroll
    for (int mt = 0; mt < 2; ++mt) {
        const int row = m0 + wm * 32 + mt * 16 + g;
        #pragma unroll
        for (int nt = 0; nt < 4; ++nt) {
            const int col = n0 + wn * 32 + nt * 8 + 2 * tig;
            const float bx = bias[col], by = bias[col + 1];
            float v0 = c[mt][nt][0] + bx, v1 = c[mt][nt][1] + by;
            float v2 = c[mt][nt][2] + bx, v3 = c[mt][nt][3] + by;
            if (rnd) {
                v0 = __uint_as_float(cvt_tf32(v0));
                v1 = __uint_as_float(cvt_tf32(v1));
                v2 = __uint_as_float(cvt_tf32(v2));
                v3 = __uint_as_float(cvt_tf32(v3));
            }
            if (trv) {
                // V scratch: transposed [b][h][d][token'], token perm16-permuted.
                // col is even, so col+1 shares the same head (col&63 <= 62).
                const int hh = col >> 6, dd = col & 63;
                const int bi = row / LL;
                const int t0 = perm16(row % LL);
                const int t1 = perm16((row + 8) % LL);   // same 16-group as row
                float* vbase = &C[(((size_t)bi * HEADS + hh) * HD + dd) * LL];
                vbase[t0]      = v0;
                vbase[LL + t0] = v1;   // d+1, same token
                vbase[t1]      = v2;
                vbase[LL + t1] = v3;
            } else if (prm) {   // K scratch: perm16 columns (scalar stores)
                const int p0c = perm16(col);
                const int p1c = perm16(col + 1);
                C[(size_t)row * N + p0c] = v0;
                C[(size_t)row * N + p1c] = v1;
                C[(size_t)(row + 8) * N + p0c] = v2;
                C[(size_t)(row + 8) * N + p1c] = v3;
            } else {
                *(float2*)&C[(size_t)row * N + col] = make_float2(v0, v1);
                *(float2*)&C[(size_t)(row + 8) * N + col] = make_float2(v2, v3);
            }
        }
    }
}

// ---------------------------------------------------------------------------
// Flash-style causal attention with relative-position terms, tf32 mma.
// CTA: 64 q-rows per (b,h); 128 threads = 4 warps; warp owns 16 q-rows.
// Q/K/V arrive pre-rounded to tf32 (GEMM epilogue), no cvt on load.
// K: perm16 columns  -> one LDS.128 feeds TWO S-loop MMAs.
// V: d-major transposed, perm16 tokens -> one LDS.128 feeds TWO PV MMAs.
// K/V smem stride 80 (= 16 mod 32): LDS.128 quarter-phases conflict-free.
// K/V cp.async double-buffered; one __syncthreads per kt-iteration.
// ---------------------------------------------------------------------------
__global__ __launch_bounds__(128) void attn_tc(
    const float* __restrict__ gq, const float* __restrict__ gk,
    const float* __restrict__ gvt, const float* __restrict__ relk,
    const float* __restrict__ relv, float* __restrict__ gctx)
{
    extern __shared__ float sm[];
    float* Qs   = sm;                  // 64*68, reused as Ps after Q frags cached
    float* Ks0  = Qs + 64 * 68;        // [2][64*80]  (perm16 k-columns)
    float* Vs0  = Ks0 + 2 * 64 * 80;   // [2][64*80]  rows = d, cols = perm16 keys
    float* prel = Vs0 + 2 * 64 * 80;   // [64][6]  (pre-scaled by 0.125 via Q)
    float* nearw = prel + 64 * 6;      // [64][5]

    const int tid = threadIdx.x;
    const int wid = tid >> 5, lane = tid & 31;
    const int g = lane >> 2, tig = lane & 3;
    const int qt = blockIdx.x;
    const int h = blockIdx.y, b = blockIdx.z;
    const int q0 = qt * 64;
    const int rw = wid * 16;           // warp's first q-row (local)
    const size_t base  = ((size_t)b * LL) * HID + (size_t)h * HD;
    const size_t vbase = ((size_t)(b * HEADS + h) * HD) * LL;   // transposed V

    const int fr = tid >> 4, fc = (tid & 15) * 4;   // tile load coords

    // Load Q tile, pre-scaled by 1/sqrt(HD)=0.125 (exact on tf32 values)
    #pragma unroll
    for (int i = 0; i < 8; ++i) {
        int r = fr + i * 8;
        float4 v = *(const float4*)&gq[base + (size_t)(q0 + r) * HID + fc];
        v.x *= 0.125f; v.y *= 0.125f; v.z *= 0.125f; v.w *= 0.125f;
        *(float4*)&Qs[r * 68 + fc] = v;
    }
    for (int idx = tid; idx < 64 * 5; idx += 128) nearw[idx] = 0.f;

    // issue cp.async for K/V tile 0 (overlaps prel + Q-frag caching)
    {
        #pragma unroll
        for (int i = 0; i < 8; ++i) {
            int r = fr + i * 8;
            cp_async16((uint32_t)__cvta_generic_to_shared(&Ks0[r * 80 + fc]),
                       &gk[base + (size_t)(r) * HID + fc]);
            cp_async16((uint32_t)__cvta_generic_to_shared(&Vs0[r * 80 + fc]),
                       &gvt[vbase + (size_t)r * LL + fc]);
        }
        cp_commit();
    }
    __syncthreads();

    // prel[r][j] = Qscaled[r] . rel_k[j]  (= 0.125 * Q.rel_k exactly)
    for (int idx = tid; idx < 64 * 6; idx += 128) {
        int r = idx / 6, j = idx % 6;
        float s = 0.f;
        #pragma unroll
        for (int d = 0; d < HD; ++d) s = fmaf(Qs[r * 68 + d], relk[j * HD + d], s);
        prel[r * 6 + j] = s;
    }

    // Cache Q A-fragments in registers (frees Qs smem for P)
    uint32_t qa[8][4];
    #pragma unroll
    for (int k8 = 0; k8 < 8; ++k8) {
        const int kc = k8 * 8;
        qa[k8][0] = fu(Qs[(rw + g    ) * 68 + kc + tig    ]);
        qa[k8][1] = fu(Qs[(rw + g + 8) * 68 + kc + tig    ]);
        qa[k8][2] = fu(Qs[(rw + g    ) * 68 + kc + tig + 4]);
        qa[k8][3] = fu(Qs[(rw + g + 8) * 68 + kc + tig + 4]);
    }

    float m0r = -1e30f, m1r = -1e30f, l0r = 0.f, l1r = 0.f;
    float o[8][4] = {};

    for (int kt = 0; kt <= qt; ++kt) {
        const int buf = kt & 1;
        float* Ks = Ks0 + buf * (64 * 80);
        float* Vs = Vs0 + buf * (64 * 80);

        // complete the single outstanding group; one barrier covers
        // load-visibility and prior-iteration buffer reuse.
        cp_wait<0>();
        __syncthreads();

        // issue next tile into buf^1 (in flight until next iteration's top)
        if (kt < qt) {
            float* Kn = Ks0 + (buf ^ 1) * (64 * 80);
            float* Vn = Vs0 + (buf ^ 1) * (64 * 80);
            const int kn = (kt + 1) * 64;
            #pragma unroll
            for (int i = 0; i < 8; ++i) {
                int r = fr + i * 8;
                cp_async16((uint32_t)__cvta_generic_to_shared(&Kn[r * 80 + fc]),
                           &gk[base + (size_t)(kn + r) * HID + fc]);
                cp_async16((uint32_t)__cvta_generic_to_shared(&Vn[r * 80 + fc]),
                           &gvt[vbase + (size_t)r * LL + kn + fc]);
            }
            cp_commit();
        }

        // S = Qscaled @ K^T  (warp: 16 x 64)
        // perm16 K: one float4 at (16*k16 + 4*tig) = logical k {tig,tig+4,tig+8,tig+12}
        float s[8][4] = {};
        #pragma unroll
        for (int k16 = 0; k16 < 4; ++k16) {
            #pragma unroll
            for (int nt = 0; nt < 8; ++nt) {
                float4 kk = *(const float4*)&Ks[(nt * 8 + g) * 80 + k16 * 16 + 4 * tig];
                mma_tf32(s[nt], qa[2*k16][0], qa[2*k16][1], qa[2*k16][2], qa[2*k16][3],
                         fu(kk.x), fu(kk.y));
                mma_tf32(s[nt], qa[2*k16+1][0], qa[2*k16+1][1], qa[2*k16+1][2], qa[2*k16+1][3],
                         fu(kk.z), fu(kk.w));
            }
        }

        const int dq = (qt - kt) * 64;
        const bool neardiag = (dq <= 64);
        const int rl0 = rw + g, rl1 = rw + g + 8;

        // bias + mask
        float rm0 = -1e30f, rm1 = -1e30f;
        #pragma unroll
        for (int nt = 0; nt < 8; ++nt) {
            #pragma unroll
            for (int e = 0; e < 4; ++e) {
                const int rl = (e < 2) ? rl0 : rl1;
                const int col = nt * 8 + 2 * tig + (e & 1);
                const int d = dq + rl - col;
                if (d < 0) s[nt][e] = -1e30f;
                else {
                    const int id = (d >= 5) ? 0 : (5 - d);
                    s[nt][e] = s[nt][e] + prel[rl * 6 + id];
                }
            }
            rm0 = fmaxf(rm0, fmaxf(s[nt][0], s[nt][1]));
            rm1 = fmaxf(rm1, fmaxf(s[nt][2], s[nt][3]));
        }
        rm0 = fmaxf(rm0, __shfl_xor_sync(0xffffffffu, rm0, 1));
        rm0 = fmaxf(rm0, __shfl_xor_sync(0xffffffffu, rm0, 2));
        rm1 = fmaxf(rm1, __shfl_xor_sync(0xffffffffu, rm1, 1));
        rm1 = fmaxf(rm1, __shfl_xor_sync(0xffffffffu, rm1, 2));

        const float mn0 = fmaxf(m0r, rm0), mn1 = fmaxf(m1r, rm1);
        const float sc0 = __expf(m0r - mn0), sc1 = __expf(m1r - mn1);
        float ls0 = 0.f, ls1 = 0.f;
        #pragma unroll
        for (int nt = 0; nt < 8; ++nt) {
            s[nt][0] = __expf(s[nt][0] - mn0);
            s[nt][1] = __expf(s[nt][1] - mn0);
            s[nt][2] = __expf(s[nt][2] - mn1);
            s[nt][3] = __expf(s[nt][3] - mn1);
            ls0 += s[nt][0] + s[nt][1];
            ls1 += s[nt][2] + s[nt][3];
        }
        ls0 += __shfl_xor_sync(0xffffffffu, ls0, 1);
        ls0 += __shfl_xor_sync(0xffffffffu, ls0, 2);
        ls1 += __shfl_xor_sync(0xffffffffu, ls1, 1);
        ls1 += __shfl_xor_sync(0xffffffffu, ls1, 2);

        m0r = mn0; m1r = mn1;
        l0r = l0r * sc0 + ls0;
        l1r = l1r * sc1 + ls1;
        #pragma unroll
        for (int dt = 0; dt < 8; ++dt) {
            o[dt][0] *= sc0; o[dt][1] *= sc0;
            o[dt][2] *= sc1; o[dt][3] *= sc1;
        }

        if (neardiag) {
            if (tig == 0) {
                #pragma unroll
                for (int dd = 0; dd < 5; ++dd) {
                    nearw[rl0 * 5 + dd] *= sc0;
                    nearw[rl1 * 5 + dd] *= sc1;
                }
            }
            __syncwarp();
            #pragma unroll
            for (int nt = 0; nt < 8; ++nt) {
                #pragma unroll
                for (int e = 0; e < 4; ++e) {
                    const int rl = (e < 2) ? rl0 : rl1;
                    const int col = nt * 8 + 2 * tig + (e & 1);
                    const int d = dq + rl - col;
                    if (d >= 0 && d < 5) nearw[rl * 5 + d] = s[nt][e];
                }
            }
        }

        // write P into Qs (reused region), tf32-rounded patterns
        #pragma unroll
        for (int nt = 0; nt < 8; ++nt) {
            uint2 p01, p23;
            p01.x = cvt_tf32(s[nt][0]); p01.y = cvt_tf32(s[nt][1]);
            p23.x = cvt_tf32(s[nt][2]); p23.y = cvt_tf32(s[nt][3]);
            *(uint2*)&Qs[rl0 * 68 + nt * 8 + 2 * tig] = p01;
            *(uint2*)&Qs[rl1 * 68 + nt * 8 + 2 * tig] = p23;
        }
        __syncwarp();

        // O += P @ V   (perm16 V: one float4 feeds two MMAs per dt)
        #pragma unroll
        for (int k16 = 0; k16 < 4; ++k16) {
            const int kc0 = k16 * 16;      // logical k-chunk 2*k16
            const int kc1 = kc0 + 8;       // logical k-chunk 2*k16+1
            uint32_t paA0 = fu(Qs[rl0 * 68 + kc0 + tig    ]);
            uint32_t paA1 = fu(Qs[rl1 * 68 + kc0 + tig    ]);
            uint32_t paA2 = fu(Qs[rl0 * 68 + kc0 + tig + 4]);
            uint32_t paA3 = fu(Qs[rl1 * 68 + kc0 + tig + 4]);
            uint32_t paB0 = fu(Qs[rl0 * 68 + kc1 + tig    ]);
            uint32_t paB1 = fu(Qs[rl1 * 68 + kc1 + tig    ]);
            uint32_t paB2 = fu(Qs[rl0 * 68 + kc1 + tig + 4]);
            uint32_t paB3 = fu(Qs[rl1 * 68 + kc1 + tig + 4]);
            #pragma unroll
            for (int dt = 0; dt < 8; ++dt) {
                float4 vv = *(const float4*)&Vs[(dt * 8 + g) * 80 + k16 * 16 + 4 * tig];
                mma_tf32(o[dt], paA0, paA1, paA2, paA3, fu(vv.x), fu(vv.y));
                mma_tf32(o[dt], paB0, paB1, paB2, paB3, fu(vv.z), fu(vv.w));
            }
        }
        // no trailing barrier: next iteration's top barrier guards reuse
    }
    __syncwarp();   // order tig==0 nearw writes before cross-lane epilogue reads

    // Epilogue: rel_v near/far trick + normalize
    const int rl0 = rw + g, rl1 = rw + g + 8;
    const float inv0 = 1.f / l0r, inv1 = 1.f / l1r;
    const float a0 = nearw[rl0*5+0], a1 = nearw[rl0*5+1], a2 = nearw[rl0*5+2],
                a3 = nearw[rl0*5+3], a4 = nearw[rl0*5+4];
    const float b0 = nearw[rl1*5+0], b1 = nearw[rl1*5+1], b2 = nearw[rl1*5+2],
                b3 = nearw[rl1*5+3], b4 = nearw[rl1*5+4];
    const float far0 = l0r - (a0 + a1 + a2 + a3 + a4);
    const float far1 = l1r - (b0 + b1 + b2 + b3 + b4);

    #pragma unroll
    for (int dt = 0; dt < 8; ++dt) {
        const int c = dt * 8 + 2 * tig;
        #pragma unroll
        for (int j = 0; j < 2; ++j) {
            const int cc = c + j;
            const float r5 = relv[5*HD+cc], r4 = relv[4*HD+cc], r3 = relv[3*HD+cc],
                        r2 = relv[2*HD+cc], r1 = relv[1*HD+cc], r0 = relv[cc];
            float e0 = a0*r5 + a1*r4 + a2*r3 + a3*r2 + a4*r1 + far0*r0;
            float e1 = b0*r5 + b1*r4 + b2*r3 + b3*r2 + b4*r1 + far1*r0;
            gctx[base + (size_t)(q0 + rl0) * HID + cc] = (o[dt][j]     + e0) * inv0;
            gctx[base + (size_t)(q0 + rl1) * HID + cc] = (o[dt][2 + j] + e1) * inv1;
        }
    }
}

extern "C" void kernel_launch(void* const* d_in, const int* in_sizes, int n_in,
                              void* d_out, int out_size) {
    (void)in_sizes; (void)n_in; (void)out_size;
    const float* query = (const float*)d_in[0];
    const float* key   = (const float*)d_in[1];
    const float* value = (const float*)d_in[2];
    const float* Wq = (const float*)d_in[3];
    const float* bq = (const float*)d_in[4];
    const float* Wk = (const float*)d_in[5];
    const float* bk = (const float*)d_in[6];
    const float* Wv = (const float*)d_in[7];
    const float* bv = (const float*)d_in[8];
    const float* Wo = (const float*)d_in[9];
    const float* bo = (const float*)d_in[10];
    const float* relk = (const float*)d_in[11];
    const float* relv = (const float*)d_in[12];

    float *pq, *pk, *pv, *pctx;
    cudaGetSymbolAddress((void**)&pq,  g_q);
    cudaGetSymbolAddress((void**)&pk,  g_k);
    cudaGetSymbolAddress((void**)&pv,  g_v);
    cudaGetSymbolAddress((void**)&pctx, g_ctx);

    const int GSMEM = 2 * (AS_STRIDE + BS_STRIDE) * (int)sizeof(uint32_t); // 55296
    cudaFuncSetAttribute(gemm_nt_tc,
                         cudaFuncAttributeMaxDynamicSharedMemorySize, GSMEM);

    // 1) QKV projections — tf32-pre-rounded; K perm16 columns; V transposed
    GArgs qkv;
    qkv.A[0] = query; qkv.W[0] = Wq; qkv.bias[0] = bq; qkv.C[0] = pq;
    qkv.round_out[0] = 1; qkv.perm_out[0] = 0; qkv.trans_out[0] = 0;
    qkv.A[1] = key;   qkv.W[1] = Wk; qkv.bias[1] = bk; qkv.C[1] = pk;
    qkv.round_out[1] = 1; qkv.perm_out[1] = 1; qkv.trans_out[1] = 0;
    qkv.A[2] = value; qkv.W[2] = Wv; qkv.bias[2] = bv; qkv.C[2] = pv;
    qkv.round_out[2] = 1; qkv.perm_out[2] = 0; qkv.trans_out[2] = 1;
    gemm_nt_tc<<<dim3(HID/64, (BB*LL)/128, 3), 256, GSMEM>>>(qkv);

    // 2) attention — 64 q-rows per CTA, 128 threads; K/V stride 80
    const int SMEM = (64*68 + 4*64*80 + 64*6 + 64*5) * (int)sizeof(float);  // 102144
    cudaFuncSetAttribute(attn_tc,
                         cudaFuncAttributeMaxDynamicSharedMemorySize, SMEM);
    attn_tc<<<dim3(LL/64, HEADS, BB), 128, SMEM>>>(pq, pk, pv, relk, relv, pctx);

    // 3) output projection — exact fp32 output
    GArgs og;
    og.A[0] = pctx; og.W[0] = Wo; og.bias[0] = bo; og.C[0] = (float*)d_out;
    og.round_out[0] = 0; og.perm_out[0] = 0; og.trans_out[0] = 0;
    og.A[1] = og.A[0]; og.W[1] = og.W[0]; og.bias[1] = og.bias[0]; og.C[1] = og.C[0];
    og.round_out[1] = 0; og.perm_out[1] = 0; og.trans_out[1] = 0;
    og.A[2] = og.A[0]; og.W[2] = og.W[0]; og.bias[2] = og.bias[0]; og.C[2] = og.C[0];
    og.round_out[2] = 0; og.perm_out[2] = 0; og.trans_out[2] = 0;
    gemm_nt_tc<<<dim3(HID/64, (BB*LL)/128, 1), 256, GSMEM>>>(og);
}